// round 10
// baseline (speedup 1.0000x reference)
#include <cuda_runtime.h>
#include <math.h>
#include <stdint.h>

#define NN   4096
#define DD   128
#define HH   128
#define EQN  16384
#define MAXE 131072
#define MAXNNZ 262144

// ---------------- device scratch ----------------
static __device__ float    g_vals[MAXE];
static __device__ float    g_aval[MAXE];
static __device__ float    g_d[NN];
static __device__ int      g_deg[NN];
static __device__ float    g_invd[NN];
static __device__ float    g_pi[NN];
static __device__ int      g_rowstart[NN + 1];
static __device__ int      g_rowpos[NN];
static __device__ int      g_cols[MAXNNZ];
static __device__ float    g_cvals[MAXNNZ];
static __device__ int      g_qcnt[NN];
static __device__ int      g_qstart[NN + 1];
static __device__ int      g_qpos[NN];
static __device__ int      g_qid[EQN];
static __device__ float    g_pval[EQN];
static __device__ double   g_G1, g_G2, g_sumpi;
static __device__ float    g_XW[NN * HH];        // X @ W1[:128,:] (fp32, exact)
static __device__ uint32_t g_W1p[HH * HH];       // frag-packed tf32(W1[128:256,:]), 8-warp layout
static __device__ uint32_t g_W2p[HH * HH];       // frag-packed tf32(W2)
static __device__ float    g_wd[HH];             // W3[:,1]-W3[:,0]
static __device__ int      g_is64;

__device__ __forceinline__ int idx_at(const int* __restrict__ p, int k, int is64) {
    return is64 ? p[2 * k] : p[k];
}
__device__ __forceinline__ uint32_t tf32r(float f) {
    uint32_t r;
    asm("cvt.rna.tf32.f32 %0, %1;" : "=r"(r) : "f"(f));
    return r;
}
__device__ __forceinline__ void mma_tf32(float* d, const uint32_t* a,
                                         uint32_t b0, uint32_t b1) {
    asm("mma.sync.aligned.m16n8k8.row.col.f32.tf32.tf32.f32 "
        "{%0,%1,%2,%3}, {%4,%5,%6,%7}, {%8,%9}, {%0,%1,%2,%3};"
        : "+f"(d[0]), "+f"(d[1]), "+f"(d[2]), "+f"(d[3])
        : "r"(a[0]), "r"(a[1]), "r"(a[2]), "r"(a[3]), "r"(b0), "r"(b1));
}

// ---------------- k_pre: init (blocks 0..15) + weight prep (16..79) + XW (80..143) ----
__global__ void __launch_bounds__(256) k_pre(const float* __restrict__ X,
                                             const int* __restrict__ AE,
                                             const float* __restrict__ W1,
                                             const float* __restrict__ W2,
                                             const float* __restrict__ W3) {
    int b = blockIdx.x, t = threadIdx.x;
    if (b < 16) {
        int i = b * 256 + t;
        g_d[i] = 1.0f;          // diagonal contribution
        g_deg[i] = 1;
        g_qcnt[i] = 0;
        if (i == 0) {
            g_G1 = 0.0; g_G2 = 0.0; g_sumpi = 0.0;
            g_is64 = (AE[1] == 0) ? 1 : 0;   // strictly upper-tri => e1>=1
        }
        return;
    }
    if (b < 80) {
        // pack weights: i = ((kt*8 + w)*32 + lane)*4 + q ; q=2j+which
        //   -> W[k = kt*8 + tig + 4*which][n = 16*w + 8*j + g]
        int i = (b - 16) * 256 + t;
        int q    = i & 3;
        int lane = (i >> 2) & 31;
        int w    = (i >> 7) & 7;
        int kt   = i >> 10;
        int tig = lane & 3, g = lane >> 2;
        int j = q >> 1, which = q & 1;
        int k = kt * 8 + tig + 4 * which;
        int n = 16 * w + 8 * j + g;
        g_W1p[i] = tf32r(W1[(size_t)(HH + k) * HH + n]);
        g_W2p[i] = tf32r(W2[(size_t)k * HH + n]);
        if (i < HH) g_wd[i] = W3[2 * i + 1] - W3[2 * i];
        return;
    }
    // ---- XW = X @ W1[0:128,:], 64 rows per block ----
    __shared__ float xs[64 * 132];
    int bx = b - 80;
    int r0 = bx * 64;
    {
        int le = t >> 2, c4 = t & 3;
        const float* xr = X + (size_t)(r0 + le) * DD + c4 * 32;
#pragma unroll
        for (int i = 0; i < 32; i++) xs[le * 132 + c4 * 32 + i] = xr[i];
    }
    __syncthreads();
    int col = t & 127, h = t >> 7;
    float acc[32];
#pragma unroll
    for (int e = 0; e < 32; e++) acc[e] = 0.0f;
    for (int k = 0; k < 128; k++) {
        float w = W1[k * 128 + col];
#pragma unroll
        for (int e = 0; e < 32; e++) acc[e] = fmaf(w, xs[(h * 32 + e) * 132 + k], acc[e]);
    }
#pragma unroll
    for (int e = 0; e < 32; e++) g_XW[(size_t)(r0 + h * 32 + e) * 128 + col] = acc[e];
}

// ---- tensor-core edge MLP: 64 edges/block, 256 threads (8 warps x 16 cols) ----
// blocks 0..63 additionally do the query row-count atomics.
#define AS 132
__global__ void __launch_bounds__(256) k_mlp(const float* __restrict__ X,
                                             const int* __restrict__ AE,
                                             const int* __restrict__ Q,
                                             const float* __restrict__ b1g,
                                             const float* __restrict__ b2g,
                                             const float* __restrict__ b3g,
                                             int E) {
    __shared__ __align__(16) uint32_t As[64 * AS];
    __shared__ int   su[64], sv[64];
    __shared__ float zsm[64 * 8];
    int t = threadIdx.x;
    int w = t >> 5, lane = t & 31;
    int g = lane >> 2, tig = lane & 3;
    int e0 = blockIdx.x * 64;
    int is64 = g_is64;

    if ((int)blockIdx.x < 64) {
        int q = blockIdx.x * 256 + t;
        atomicAdd(&g_qcnt[idx_at(Q, 2 * q, is64)], 1);
    }

    // ---- edge indices
    if (t < 64) {
        int e = e0 + t;
        int u = 0, v = 0;
        if (e < E) { u = idx_at(AE, 2 * e, is64); v = idx_at(AE, 2 * e + 1, is64); }
        su[t] = u; sv[t] = v;
    }
    __syncthreads();

    // ---- feature build: warp w covers edges [8w, 8w+8)
#pragma unroll
    for (int i = 0; i < 8; i++) {
        int le = w * 8 + i;
        float4 xu = ((const float4*)(X + (size_t)su[le] * DD))[lane];
        float4 xv = ((const float4*)(X + (size_t)sv[le] * DD))[lane];
        uint4 f;
        f.x = tf32r(fabsf(xu.x - xv.x));
        f.y = tf32r(fabsf(xu.y - xv.y));
        f.z = tf32r(fabsf(xu.z - xv.z));
        f.w = tf32r(fabsf(xu.w - xv.w));
        *(uint4*)&As[le * AS + 4 * lane] = f;
    }
    __syncthreads();

    float acc[4][2][4];   // [m-tile][n-subtile j][frag]; warp owns cols [16w,16w+16)

    // ---- layer 1 init: b1 + XW[u] + XW[v]  (fp32 exact)
    {
        float2 bb[2];
#pragma unroll
        for (int j = 0; j < 2; j++) bb[j] = *(const float2*)&b1g[16 * w + 8 * j + 2 * tig];
#pragma unroll
        for (int mt = 0; mt < 4; mt++) {
            int r0 = mt * 16 + g, r1 = r0 + 8;
            int u0 = su[r0], v0 = sv[r0], u1 = su[r1], v1 = sv[r1];
#pragma unroll
            for (int j = 0; j < 2; j++) {
                int c = 16 * w + 8 * j + 2 * tig;
                float2 xu0 = *(const float2*)&g_XW[(size_t)u0 * 128 + c];
                float2 xv0 = *(const float2*)&g_XW[(size_t)v0 * 128 + c];
                float2 xu1 = *(const float2*)&g_XW[(size_t)u1 * 128 + c];
                float2 xv1 = *(const float2*)&g_XW[(size_t)v1 * 128 + c];
                acc[mt][j][0] = bb[j].x + xu0.x + xv0.x;
                acc[mt][j][1] = bb[j].y + xu0.y + xv0.y;
                acc[mt][j][2] = bb[j].x + xu1.x + xv1.x;
                acc[mt][j][3] = bb[j].y + xu1.y + xv1.y;
            }
        }
    }

    // ---- layer 1 mma
#pragma unroll
    for (int kt = 0; kt < 16; kt++) {
        int kc = kt * 8 + tig;
        uint32_t a[4][4];
#pragma unroll
        for (int mt = 0; mt < 4; mt++) {
            int r0 = mt * 16 + g;
            a[mt][0] = As[r0 * AS + kc];
            a[mt][1] = As[(r0 + 8) * AS + kc];
            a[mt][2] = As[r0 * AS + kc + 4];
            a[mt][3] = As[(r0 + 8) * AS + kc + 4];
        }
        uint4 wA = *(const uint4*)(g_W1p + ((((kt * 8 + w) * 32 + lane)) << 2));
#pragma unroll
        for (int mt = 0; mt < 4; mt++) {
            mma_tf32(acc[mt][0], a[mt], wA.x, wA.y);
            mma_tf32(acc[mt][1], a[mt], wA.z, wA.w);
        }
    }
    __syncthreads();

    // relu -> h1 (tf32) back into As
#pragma unroll
    for (int mt = 0; mt < 4; mt++) {
        int r0 = mt * 16 + g;
#pragma unroll
        for (int j = 0; j < 2; j++) {
            int c = 16 * w + 8 * j + 2 * tig;
            uint2 p0, p1;
            p0.x = tf32r(fmaxf(acc[mt][j][0], 0.0f));
            p0.y = tf32r(fmaxf(acc[mt][j][1], 0.0f));
            p1.x = tf32r(fmaxf(acc[mt][j][2], 0.0f));
            p1.y = tf32r(fmaxf(acc[mt][j][3], 0.0f));
            *(uint2*)&As[r0 * AS + c] = p0;
            *(uint2*)&As[(r0 + 8) * AS + c] = p1;
        }
    }
    __syncthreads();

    // ---- layer 2 init: b2
#pragma unroll
    for (int j = 0; j < 2; j++) {
        float2 bb = *(const float2*)&b2g[16 * w + 8 * j + 2 * tig];
#pragma unroll
        for (int mt = 0; mt < 4; mt++) {
            acc[mt][j][0] = bb.x; acc[mt][j][1] = bb.y;
            acc[mt][j][2] = bb.x; acc[mt][j][3] = bb.y;
        }
    }
    // ---- layer 2 mma
#pragma unroll
    for (int kt = 0; kt < 16; kt++) {
        int kc = kt * 8 + tig;
        uint32_t a[4][4];
#pragma unroll
        for (int mt = 0; mt < 4; mt++) {
            int r0 = mt * 16 + g;
            a[mt][0] = As[r0 * AS + kc];
            a[mt][1] = As[(r0 + 8) * AS + kc];
            a[mt][2] = As[r0 * AS + kc + 4];
            a[mt][3] = As[(r0 + 8) * AS + kc + 4];
        }
        uint4 wA = *(const uint4*)(g_W2p + ((((kt * 8 + w) * 32 + lane)) << 2));
#pragma unroll
        for (int mt = 0; mt < 4; mt++) {
            mma_tf32(acc[mt][0], a[mt], wA.x, wA.y);
            mma_tf32(acc[mt][1], a[mt], wA.z, wA.w);
        }
    }

    // ---- head: z = relu(h2) . wd  (partial over this warp's 16 cols)
    float z[4][2];
#pragma unroll
    for (int mt = 0; mt < 4; mt++) { z[mt][0] = 0.0f; z[mt][1] = 0.0f; }
    {
        float2 wdj[2];
#pragma unroll
        for (int j = 0; j < 2; j++) wdj[j] = *(const float2*)&g_wd[16 * w + 8 * j + 2 * tig];
#pragma unroll
        for (int mt = 0; mt < 4; mt++)
#pragma unroll
            for (int j = 0; j < 2; j++) {
                z[mt][0] = fmaf(fmaxf(acc[mt][j][0], 0.0f), wdj[j].x,
                           fmaf(fmaxf(acc[mt][j][1], 0.0f), wdj[j].y, z[mt][0]));
                z[mt][1] = fmaf(fmaxf(acc[mt][j][2], 0.0f), wdj[j].x,
                           fmaf(fmaxf(acc[mt][j][3], 0.0f), wdj[j].y, z[mt][1]));
            }
    }
#pragma unroll
    for (int mt = 0; mt < 4; mt++)
#pragma unroll
        for (int h = 0; h < 2; h++) {
            z[mt][h] += __shfl_xor_sync(0xffffffffu, z[mt][h], 1);
            z[mt][h] += __shfl_xor_sync(0xffffffffu, z[mt][h], 2);
        }
    if (tig == 0) {
#pragma unroll
        for (int mt = 0; mt < 4; mt++)
#pragma unroll
            for (int h = 0; h < 2; h++)
                zsm[(mt * 16 + g + 8 * h) * 8 + w] = z[mt][h];
    }
    __syncthreads();
    if (t < 64) {
        int e = e0 + t;
        if (e < E) {
            const float* zp = &zsm[8 * t];
            float zz = ((zp[0] + zp[1]) + (zp[2] + zp[3]))
                     + ((zp[4] + zp[5]) + (zp[6] + zp[7]))
                     + (b3g[1] - b3g[0]);
            g_vals[e] = 1.0f / (1.0f + __expf(-zz));
        }
    }
}

// per-edge A_enh value + degree/rowsum accumulation (proven R3-R7 path)
__global__ void k_edge(const float* __restrict__ A, const float* __restrict__ S,
                       const int* __restrict__ AE, int E) {
    int e = blockIdx.x * 256 + threadIdx.x;
    if (e >= E) return;
    int is64 = g_is64;
    int u = idx_at(AE, 2 * e, is64), v = idx_at(AE, 2 * e + 1, is64);
    size_t idx = ((size_t)u << 12) + (size_t)v;
    float a = 0.5f * A[idx] + 0.25f * g_vals[e] + 0.25f * S[idx];
    g_aval[e] = a;
    atomicAdd(&g_d[u], a);
    atomicAdd(&g_d[v], a);
    atomicAdd(&g_deg[u], 1);
    atomicAdd(&g_deg[v], 1);
}

// scans (rows, query rows) + sumd + pi/invd/diag-CSR + sumpi. single block, 1024 thr.
__global__ void __launch_bounds__(1024) k_scan() {
    __shared__ int    wsum[32];
    __shared__ float  wfs[32];
    __shared__ double wds[32];
    __shared__ float  s_sumd;
    int t = threadIdx.x;
    int lane = t & 31, wid = t >> 5;

    int   deg[4];
    float dv[4];
#pragma unroll
    for (int j = 0; j < 4; j++) {
        deg[j] = g_deg[4 * t + j];
        dv[j] = g_d[4 * t + j];
    }

    // ---- row degree scan ----
    {
        int s = deg[0] + deg[1] + deg[2] + deg[3];
        int incl = s;
#pragma unroll
        for (int o = 1; o < 32; o <<= 1) {
            int x = __shfl_up_sync(0xffffffffu, incl, o);
            if (lane >= o) incl += x;
        }
        if (lane == 31) wsum[wid] = incl;
        __syncthreads();
        if (wid == 0) {
            int ws = wsum[lane];
            int wi = ws;
#pragma unroll
            for (int o = 1; o < 32; o <<= 1) {
                int x = __shfl_up_sync(0xffffffffu, wi, o);
                if (lane >= o) wi += x;
            }
            wsum[lane] = wi - ws;
        }
        __syncthreads();
        int run = wsum[wid] + incl - s;
#pragma unroll
        for (int j = 0; j < 4; j++) { g_rowstart[4 * t + j] = run; g_rowpos[4 * t + j] = run; run += deg[j]; }
        if (t == 1023) g_rowstart[NN] = run;
    }
    __syncthreads();

    // ---- query count scan ----
    {
        int v[4], s = 0;
#pragma unroll
        for (int j = 0; j < 4; j++) { v[j] = g_qcnt[4 * t + j]; s += v[j]; }
        int incl = s;
#pragma unroll
        for (int o = 1; o < 32; o <<= 1) {
            int x = __shfl_up_sync(0xffffffffu, incl, o);
            if (lane >= o) incl += x;
        }
        if (lane == 31) wsum[wid] = incl;
        __syncthreads();
        if (wid == 0) {
            int ws = wsum[lane];
            int wi = ws;
#pragma unroll
            for (int o = 1; o < 32; o <<= 1) {
                int x = __shfl_up_sync(0xffffffffu, wi, o);
                if (lane >= o) wi += x;
            }
            wsum[lane] = wi - ws;
        }
        __syncthreads();
        int run = wsum[wid] + incl - s;
#pragma unroll
        for (int j = 0; j < 4; j++) { g_qstart[4 * t + j] = run; g_qpos[4 * t + j] = run; run += v[j]; }
        if (t == 1023) g_qstart[NN] = run;
    }
    __syncthreads();

    // ---- sumd ----
    {
        float fs = dv[0] + dv[1] + dv[2] + dv[3];
#pragma unroll
        for (int o = 16; o; o >>= 1) fs += __shfl_xor_sync(0xffffffffu, fs, o);
        if (lane == 0) wfs[wid] = fs;
        __syncthreads();
        if (t == 0) {
            float tot = 0.0f;
#pragma unroll
            for (int i2 = 0; i2 < 32; i2++) tot += wfs[i2];
            s_sumd = tot;
        }
    }
    __syncthreads();

    // ---- pi, invd, diag CSR, sumpi ----
    {
        float sumd = s_sumd;
        double sp = 0.0;
#pragma unroll
        for (int j = 0; j < 4; j++) {
            int i = 4 * t + j;
            float p = dv[j] / sumd;
            g_pi[i] = p;
            g_invd[i] = 1.0f / dv[j];
            sp += (double)p;
            int idx = g_rowpos[i];
            g_cols[idx] = i;
            g_cvals[idx] = 1.0f;
            g_rowpos[i] = idx + 1;
        }
#pragma unroll
        for (int o = 16; o; o >>= 1) sp += __shfl_xor_sync(0xffffffffu, sp, o);
        if (lane == 0) wds[wid] = sp;
        __syncthreads();
        if (t == 0) {
            double tot = 0.0;
#pragma unroll
            for (int i2 = 0; i2 < 32; i2++) tot += wds[i2];
            g_sumpi = tot;
        }
    }
}

// fused: CSR scatter + query-id scatter
__global__ void k_scatter(const int* __restrict__ AE, const int* __restrict__ Q,
                          int E, int EB) {
    int is64 = g_is64;
    if ((int)blockIdx.x < EB) {
        int e = blockIdx.x * 256 + threadIdx.x;
        if (e >= E) return;
        int u = idx_at(AE, 2 * e, is64), v = idx_at(AE, 2 * e + 1, is64);
        float a = g_aval[e];
        int i1 = atomicAdd(&g_rowpos[u], 1); g_cols[i1] = v; g_cvals[i1] = a;
        int i2 = atomicAdd(&g_rowpos[v], 1); g_cols[i2] = u; g_cvals[i2] = a;
    } else {
        int q = (blockIdx.x - EB) * 256 + threadIdx.x;
        if (q >= EQN) return;
        int i = idx_at(Q, 2 * q, is64);
        int idx = atomicAdd(&g_qpos[i], 1);
        g_qid[idx] = q;
    }
}

__global__ void __launch_bounds__(256) k_row(const int* __restrict__ Q) {
    __shared__ float acc[NN];
    __shared__ float s1[8], s2[8];
    int i = blockIdx.x;
    int t = threadIdx.x;
    for (int c = t; c < NN; c += 256) acc[c] = 0.0f;
    __syncthreads();

    int rs = g_rowstart[i], re = g_rowstart[i + 1];
    float idi = g_invd[i];
    int warp = t >> 5, lane = t & 31;
    for (int jj = rs + warp; jj < re; jj += 8) {
        int j = g_cols[jj];
        float sscale = g_cvals[jj] * idi * g_invd[j];
        int js = g_rowstart[j], je = g_rowstart[j + 1];
        for (int kk = js + lane; kk < je; kk += 32)
            atomicAdd(&acc[g_cols[kk]], sscale * g_cvals[kk]);
    }
    __syncthreads();

    float srow = 0.0f, ssq = 0.0f;
    for (int c = t; c < NN; c += 256) {
        float a = acc[c];
        srow += a;
        float dd = a - g_pi[c];
        ssq = fmaf(dd, dd, ssq);
    }
#pragma unroll
    for (int o = 16; o; o >>= 1) {
        srow += __shfl_down_sync(0xffffffffu, srow, o);
        ssq  += __shfl_down_sync(0xffffffffu, ssq, o);
    }
    if (lane == 0) { s1[warp] = srow; s2[warp] = ssq; }
    __syncthreads();
    if (t == 0) {
        float S1 = 0.0f, S2 = 0.0f;
#pragma unroll
        for (int w2 = 0; w2 < 8; w2++) { S1 += s1[w2]; S2 += s2[w2]; }
        float pii = g_pi[i];
        atomicAdd(&g_G1, (double)pii * (double)S1);
        atomicAdd(&g_G2, (double)pii * (double)pii * (double)S2);
    }
    int is64 = g_is64;
    int qs = g_qstart[i], qe = g_qstart[i + 1];
    for (int q = qs + t; q < qe; q += 256) {
        int qq = g_qid[q];
        int j1 = idx_at(Q, 2 * qq + 1, is64);
        g_pval[qq] = acc[j1];
    }
}

__global__ void k_final(const int* __restrict__ Q, float* __restrict__ out) {
    int q = blockIdx.x * 256 + threadIdx.x;
    if (q >= EQN) return;
    int is64 = g_is64;
    double n2 = (double)NN * (double)NN;
    double sp = g_sumpi;
    double mean = (g_G1 - sp * sp) / n2;
    double var = (g_G2 - n2 * mean * mean) / (n2 - 1.0);
    double istd = rsqrt(var);
    int i = idx_at(Q, 2 * q, is64), j = idx_at(Q, 2 * q + 1, is64);
    double r = (double)g_pi[i] * ((double)g_pval[q] - (double)g_pi[j]);
    out[q] = (float)((r - mean) * istd);
}

// ---------------- launch ----------------
extern "C" void kernel_launch(void* const* d_in, const int* in_sizes, int n_in,
                              void* d_out, int out_size) {
    const float* X  = (const float*)d_in[0];
    const float* A  = (const float*)d_in[1];
    const float* S  = (const float*)d_in[2];
    const int*   AE = (const int*)d_in[4];
    const int*   Q  = (const int*)d_in[5];
    const float* W1 = (const float*)d_in[6];
    const float* b1 = (const float*)d_in[7];
    const float* W2 = (const float*)d_in[8];
    const float* b2 = (const float*)d_in[9];
    const float* W3 = (const float*)d_in[10];
    const float* b3 = (const float*)d_in[11];
    float* out = (float*)d_out;
    int E = in_sizes[4] / 2;
    int EB = (E + 255) / 256;
    int QB = EQN / 256;

    k_pre<<<144, 256>>>(X, AE, W1, W2, W3);
    k_mlp<<<(E + 63) / 64, 256>>>(X, AE, Q, b1, b2, b3, E);
    k_edge<<<EB, 256>>>(A, S, AE, E);
    k_scan<<<1, 1024>>>();
    k_scatter<<<EB + QB, 256>>>(AE, Q, E, EB);
    k_row<<<NN, 256>>>(Q);
    k_final<<<QB, 256>>>(Q, out);
}

// round 13
// speedup vs baseline: 1.0206x; 1.0206x over previous
#include <cuda_runtime.h>
#include <math.h>
#include <stdint.h>

#define NN   4096
#define DD   128
#define HH   128
#define EQN  16384
#define MAXE 131072
#define MAXNNZ 262144

// ---------------- device scratch ----------------
static __device__ float    g_vals[MAXE];
static __device__ float    g_aval[MAXE];
static __device__ float    g_d[NN];
static __device__ int      g_deg[NN];
static __device__ float    g_invd[NN];
static __device__ float    g_pi[NN];
static __device__ int      g_rowstart[NN + 1];
static __device__ int      g_rowpos[NN];
static __device__ int      g_cols[MAXNNZ];
static __device__ float    g_cvals[MAXNNZ];
static __device__ int      g_qcnt[NN];
static __device__ int      g_qstart[NN + 1];
static __device__ int      g_qpos[NN];
static __device__ int      g_qid[EQN];
static __device__ float    g_pval[EQN];
static __device__ double   g_G1, g_G2, g_sumpi;
static __device__ float    g_XW[NN * HH];        // X @ W1[:128,:] (fp32, exact)
static __device__ uint32_t g_W1p[HH * HH];       // frag-packed tf32(W1[128:256,:]), 4-warp layout
static __device__ uint32_t g_W2p[HH * HH];       // frag-packed tf32(W2)
static __device__ float    g_wd[HH];             // W3[:,1]-W3[:,0]
static __device__ int      g_is64;

__device__ __forceinline__ int idx_at(const int* __restrict__ p, int k) {
    return g_is64 ? p[2 * k] : p[k];
}
__device__ __forceinline__ uint32_t tf32r(float f) {
    uint32_t r;
    asm("cvt.rna.tf32.f32 %0, %1;" : "=r"(r) : "f"(f));
    return r;
}
__device__ __forceinline__ void mma_tf32(float* d, const uint32_t* a,
                                         uint32_t b0, uint32_t b1) {
    asm("mma.sync.aligned.m16n8k8.row.col.f32.tf32.tf32.f32 "
        "{%0,%1,%2,%3}, {%4,%5,%6,%7}, {%8,%9}, {%0,%1,%2,%3};"
        : "+f"(d[0]), "+f"(d[1]), "+f"(d[2]), "+f"(d[3])
        : "r"(a[0]), "r"(a[1]), "r"(a[2]), "r"(a[3]), "r"(b0), "r"(b1));
}

// ---------------- k_pre: init (blocks 0..15) + weight prep (16..79) + XW (80..143) ----
__global__ void __launch_bounds__(256) k_pre(const float* __restrict__ X,
                                             const int* __restrict__ AE,
                                             const float* __restrict__ W1,
                                             const float* __restrict__ W2,
                                             const float* __restrict__ W3) {
    int b = blockIdx.x, t = threadIdx.x;
    if (b < 16) {
        int i = b * 256 + t;
        g_d[i] = 1.0f;          // diagonal contribution
        g_deg[i] = 1;
        g_qcnt[i] = 0;
        if (i == 0) {
            g_G1 = 0.0; g_G2 = 0.0; g_sumpi = 0.0;
            g_is64 = (AE[1] == 0) ? 1 : 0;   // strictly upper-tri => e1>=1
        }
        return;
    }
    if (b < 80) {
        // pack: i = ((kt*4 + w)*32 + lane)*8 + q ; lane=4g+tig ; q: j=q>>1, which=q&1
        //   -> W[k = kt*8 + tig + 4*which][n = 32*w + 8*j + g]
        int i = (b - 16) * 256 + t;
        int q    = i & 7;
        int lane = (i >> 3) & 31;
        int w    = (i >> 8) & 3;
        int kt   = i >> 10;
        int tig = lane & 3, g = lane >> 2;
        int j = q >> 1, which = q & 1;
        int k = kt * 8 + tig + 4 * which;
        int n = 32 * w + 8 * j + g;
        g_W1p[i] = tf32r(W1[(size_t)(HH + k) * HH + n]);
        g_W2p[i] = tf32r(W2[(size_t)k * HH + n]);
        if (i < HH) g_wd[i] = W3[2 * i + 1] - W3[2 * i];
        return;
    }
    // ---- XW = X @ W1[0:128,:], 64 rows per block ----
    __shared__ float xs[64 * 132];
    int bx = b - 80;
    int r0 = bx * 64;
    {
        int le = t >> 2, c4 = t & 3;
        const float* xr = X + (size_t)(r0 + le) * DD + c4 * 32;
#pragma unroll
        for (int i = 0; i < 32; i++) xs[le * 132 + c4 * 32 + i] = xr[i];
    }
    __syncthreads();
    int col = t & 127, h = t >> 7;
    float acc[32];
#pragma unroll
    for (int e = 0; e < 32; e++) acc[e] = 0.0f;
    for (int k = 0; k < 128; k++) {
        float w = W1[k * 128 + col];
#pragma unroll
        for (int e = 0; e < 32; e++) acc[e] = fmaf(w, xs[(h * 32 + e) * 132 + k], acc[e]);
    }
#pragma unroll
    for (int e = 0; e < 32; e++) g_XW[(size_t)(r0 + h * 32 + e) * 128 + col] = acc[e];
}

// ---- tensor-core edge MLP (verbatim R7): 64 edges/block, 128 threads ----
#define AS 132
__global__ void __launch_bounds__(128) k_mlp(const float* __restrict__ X,
                                             const int* __restrict__ AE,
                                             const float* __restrict__ b1g,
                                             const float* __restrict__ b2g,
                                             const float* __restrict__ b3g,
                                             int E) {
    __shared__ __align__(16) uint32_t As[64 * AS];   // features (tf32) -> h1 (tf32)
    __shared__ int   su[64], sv[64];
    __shared__ float zsm[64 * 4];
    int t = threadIdx.x;
    int w = t >> 5, lane = t & 31;
    int g = lane >> 2, tig = lane & 3;
    int e0 = blockIdx.x * 64;

    // ---- edge indices: warp w covers edges [16w,16w+16)
    if (lane < 16) {
        int le = w * 16 + lane;
        int e = e0 + le;
        int u = 0, v = 0;
        if (e < E) { u = idx_at(AE, 2 * e); v = idx_at(AE, 2 * e + 1); }
        su[le] = u; sv[le] = v;
    }
    __syncwarp();

    // ---- feature build (coalesced row loads)
#pragma unroll 4
    for (int i = 0; i < 16; i++) {
        int le = w * 16 + i;
        float4 xu = ((const float4*)(X + (size_t)su[le] * DD))[lane];
        float4 xv = ((const float4*)(X + (size_t)sv[le] * DD))[lane];
        uint4 f;
        f.x = tf32r(fabsf(xu.x - xv.x));
        f.y = tf32r(fabsf(xu.y - xv.y));
        f.z = tf32r(fabsf(xu.z - xv.z));
        f.w = tf32r(fabsf(xu.w - xv.w));
        *(uint4*)&As[le * AS + 4 * lane] = f;
    }
    __syncthreads();

    float acc[4][4][4];   // [m-tile][n-subtile j][frag]

    // ---- layer 1 init: b1 + XW[u] + XW[v]  (fp32 exact)
    {
        float2 bb[4];
#pragma unroll
        for (int j = 0; j < 4; j++) bb[j] = *(const float2*)&b1g[32 * w + 8 * j + 2 * tig];
#pragma unroll
        for (int mt = 0; mt < 4; mt++) {
            int r0 = mt * 16 + g, r1 = r0 + 8;
            int u0 = su[r0], v0 = sv[r0], u1 = su[r1], v1 = sv[r1];
#pragma unroll
            for (int j = 0; j < 4; j++) {
                int c = 32 * w + 8 * j + 2 * tig;
                float2 xu0 = *(const float2*)&g_XW[(size_t)u0 * 128 + c];
                float2 xv0 = *(const float2*)&g_XW[(size_t)v0 * 128 + c];
                float2 xu1 = *(const float2*)&g_XW[(size_t)u1 * 128 + c];
                float2 xv1 = *(const float2*)&g_XW[(size_t)v1 * 128 + c];
                acc[mt][j][0] = bb[j].x + xu0.x + xv0.x;
                acc[mt][j][1] = bb[j].y + xu0.y + xv0.y;
                acc[mt][j][2] = bb[j].x + xu1.x + xv1.x;
                acc[mt][j][3] = bb[j].y + xu1.y + xv1.y;
            }
        }
    }

    // ---- layer 1 mma
#pragma unroll
    for (int kt = 0; kt < 16; kt++) {
        int kc = kt * 8 + tig;
        uint32_t a[4][4];
#pragma unroll
        for (int mt = 0; mt < 4; mt++) {
            int r0 = mt * 16 + g;
            a[mt][0] = As[r0 * AS + kc];
            a[mt][1] = As[(r0 + 8) * AS + kc];
            a[mt][2] = As[r0 * AS + kc + 4];
            a[mt][3] = As[(r0 + 8) * AS + kc + 4];
        }
        const uint4* Wp = (const uint4*)(g_W1p + (((kt * 4 + w) * 32 + lane) << 3));
        uint4 wA = Wp[0], wB = Wp[1];
#pragma unroll
        for (int mt = 0; mt < 4; mt++) {
            mma_tf32(acc[mt][0], a[mt], wA.x, wA.y);
            mma_tf32(acc[mt][1], a[mt], wA.z, wA.w);
            mma_tf32(acc[mt][2], a[mt], wB.x, wB.y);
            mma_tf32(acc[mt][3], a[mt], wB.z, wB.w);
        }
    }
    __syncthreads();   // all warps done reading features

    // relu -> h1 (tf32) back into As
#pragma unroll
    for (int mt = 0; mt < 4; mt++) {
        int r0 = mt * 16 + g;
#pragma unroll
        for (int j = 0; j < 4; j++) {
            int c = 32 * w + 8 * j + 2 * tig;
            uint2 p0, p1;
            p0.x = tf32r(fmaxf(acc[mt][j][0], 0.0f));
            p0.y = tf32r(fmaxf(acc[mt][j][1], 0.0f));
            p1.x = tf32r(fmaxf(acc[mt][j][2], 0.0f));
            p1.y = tf32r(fmaxf(acc[mt][j][3], 0.0f));
            *(uint2*)&As[r0 * AS + c] = p0;
            *(uint2*)&As[(r0 + 8) * AS + c] = p1;
        }
    }
    __syncthreads();

    // ---- layer 2 init: b2
    {
#pragma unroll
        for (int j = 0; j < 4; j++) {
            float2 bb = *(const float2*)&b2g[32 * w + 8 * j + 2 * tig];
#pragma unroll
            for (int mt = 0; mt < 4; mt++) {
                acc[mt][j][0] = bb.x; acc[mt][j][1] = bb.y;
                acc[mt][j][2] = bb.x; acc[mt][j][3] = bb.y;
            }
        }
    }
    // ---- layer 2 mma
#pragma unroll
    for (int kt = 0; kt < 16; kt++) {
        int kc = kt * 8 + tig;
        uint32_t a[4][4];
#pragma unroll
        for (int mt = 0; mt < 4; mt++) {
            int r0 = mt * 16 + g;
            a[mt][0] = As[r0 * AS + kc];
            a[mt][1] = As[(r0 + 8) * AS + kc];
            a[mt][2] = As[r0 * AS + kc + 4];
            a[mt][3] = As[(r0 + 8) * AS + kc + 4];
        }
        const uint4* Wp = (const uint4*)(g_W2p + (((kt * 4 + w) * 32 + lane) << 3));
        uint4 wA = Wp[0], wB = Wp[1];
#pragma unroll
        for (int mt = 0; mt < 4; mt++) {
            mma_tf32(acc[mt][0], a[mt], wA.x, wA.y);
            mma_tf32(acc[mt][1], a[mt], wA.z, wA.w);
            mma_tf32(acc[mt][2], a[mt], wB.x, wB.y);
            mma_tf32(acc[mt][3], a[mt], wB.z, wB.w);
        }
    }

    // ---- head: z = relu(h2) . wd  (partial over this warp's 32 cols)
    float z[4][2];
#pragma unroll
    for (int mt = 0; mt < 4; mt++) { z[mt][0] = 0.0f; z[mt][1] = 0.0f; }
    {
        float2 wdj[4];
#pragma unroll
        for (int j = 0; j < 4; j++) wdj[j] = *(const float2*)&g_wd[32 * w + 8 * j + 2 * tig];
#pragma unroll
        for (int mt = 0; mt < 4; mt++)
#pragma unroll
            for (int j = 0; j < 4; j++) {
                z[mt][0] = fmaf(fmaxf(acc[mt][j][0], 0.0f), wdj[j].x,
                           fmaf(fmaxf(acc[mt][j][1], 0.0f), wdj[j].y, z[mt][0]));
                z[mt][1] = fmaf(fmaxf(acc[mt][j][2], 0.0f), wdj[j].x,
                           fmaf(fmaxf(acc[mt][j][3], 0.0f), wdj[j].y, z[mt][1]));
            }
    }
#pragma unroll
    for (int mt = 0; mt < 4; mt++)
#pragma unroll
        for (int h = 0; h < 2; h++) {
            z[mt][h] += __shfl_xor_sync(0xffffffffu, z[mt][h], 1);
            z[mt][h] += __shfl_xor_sync(0xffffffffu, z[mt][h], 2);
        }
    if (tig == 0) {
#pragma unroll
        for (int mt = 0; mt < 4; mt++)
#pragma unroll
            for (int h = 0; h < 2; h++)
                zsm[(mt * 16 + g + 8 * h) * 4 + w] = z[mt][h];
    }
    __syncthreads();
    if (t < 64) {
        int e = e0 + t;
        if (e < E) {
            float zz = zsm[4 * t] + zsm[4 * t + 1] + zsm[4 * t + 2] + zsm[4 * t + 3]
                     + (b3g[1] - b3g[0]);
            g_vals[e] = 1.0f / (1.0f + __expf(-zz));
        }
    }
}

// fused: edge A_enh accumulation + query row counts (verbatim R5-R7)
__global__ void k_edge_qcnt(const float* __restrict__ A, const float* __restrict__ S,
                            const int* __restrict__ AE, const int* __restrict__ Q,
                            int E, int EB) {
    if ((int)blockIdx.x < EB) {
        int e = blockIdx.x * 256 + threadIdx.x;
        if (e >= E) return;
        int u = idx_at(AE, 2 * e), v = idx_at(AE, 2 * e + 1);
        size_t idx = ((size_t)u << 12) + (size_t)v;
        float a = 0.5f * A[idx] + 0.25f * g_vals[e] + 0.25f * S[idx];
        g_aval[e] = a;
        atomicAdd(&g_d[u], a);
        atomicAdd(&g_d[v], a);
        atomicAdd(&g_deg[u], 1);
        atomicAdd(&g_deg[v], 1);
    } else {
        int q = (blockIdx.x - EB) * 256 + threadIdx.x;
        if (q >= EQN) return;
        atomicAdd(&g_qcnt[idx_at(Q, 2 * q)], 1);
    }
}

// scans (rows, query rows) + sumd + pi/invd/diag-CSR + sumpi. single block, 1024 thr.
__global__ void __launch_bounds__(1024) k_scan() {
    __shared__ int    wsum[32];
    __shared__ float  wfs[32];
    __shared__ double wds[32];
    __shared__ float  s_sumd;
    int t = threadIdx.x;
    int lane = t & 31, wid = t >> 5;

    int   deg[4];
    float dv[4];
#pragma unroll
    for (int j = 0; j < 4; j++) {
        deg[j] = g_deg[4 * t + j];
        dv[j] = g_d[4 * t + j];
    }

    // ---- row degree scan ----
    {
        int s = deg[0] + deg[1] + deg[2] + deg[3];
        int incl = s;
#pragma unroll
        for (int o = 1; o < 32; o <<= 1) {
            int x = __shfl_up_sync(0xffffffffu, incl, o);
            if (lane >= o) incl += x;
        }
        if (lane == 31) wsum[wid] = incl;
        __syncthreads();
        if (wid == 0) {
            int ws = wsum[lane];
            int wi = ws;
#pragma unroll
            for (int o = 1; o < 32; o <<= 1) {
                int x = __shfl_up_sync(0xffffffffu, wi, o);
                if (lane >= o) wi += x;
            }
            wsum[lane] = wi - ws;
        }
        __syncthreads();
        int run = wsum[wid] + incl - s;
#pragma unroll
        for (int j = 0; j < 4; j++) { g_rowstart[4 * t + j] = run; g_rowpos[4 * t + j] = run; run += deg[j]; }
        if (t == 1023) g_rowstart[NN] = run;
    }
    __syncthreads();

    // ---- query count scan ----
    {
        int v[4], s = 0;
#pragma unroll
        for (int j = 0; j < 4; j++) { v[j] = g_qcnt[4 * t + j]; s += v[j]; }
        int incl = s;
#pragma unroll
        for (int o = 1; o < 32; o <<= 1) {
            int x = __shfl_up_sync(0xffffffffu, incl, o);
            if (lane >= o) incl += x;
        }
        if (lane == 31) wsum[wid] = incl;
        __syncthreads();
        if (wid == 0) {
            int ws = wsum[lane];
            int wi = ws;
#pragma unroll
            for (int o = 1; o < 32; o <<= 1) {
                int x = __shfl_up_sync(0xffffffffu, wi, o);
                if (lane >= o) wi += x;
            }
            wsum[lane] = wi - ws;
        }
        __syncthreads();
        int run = wsum[wid] + incl - s;
#pragma unroll
        for (int j = 0; j < 4; j++) { g_qstart[4 * t + j] = run; g_qpos[4 * t + j] = run; run += v[j]; }
        if (t == 1023) g_qstart[NN] = run;
    }
    __syncthreads();

    // ---- sumd ----
    {
        float fs = dv[0] + dv[1] + dv[2] + dv[3];
#pragma unroll
        for (int o = 16; o; o >>= 1) fs += __shfl_xor_sync(0xffffffffu, fs, o);
        if (lane == 0) wfs[wid] = fs;
        __syncthreads();
        if (t == 0) {
            float tot = 0.0f;
#pragma unroll
            for (int i2 = 0; i2 < 32; i2++) tot += wfs[i2];
            s_sumd = tot;
        }
    }
    __syncthreads();

    // ---- pi, invd, diag CSR, sumpi ----
    {
        float sumd = s_sumd;
        double sp = 0.0;
#pragma unroll
        for (int j = 0; j < 4; j++) {
            int i = 4 * t + j;
            float p = dv[j] / sumd;
            g_pi[i] = p;
            g_invd[i] = 1.0f / dv[j];
            sp += (double)p;
            int idx = g_rowpos[i];
            g_cols[idx] = i;
            g_cvals[idx] = 1.0f;
            g_rowpos[i] = idx + 1;
        }
#pragma unroll
        for (int o = 16; o; o >>= 1) sp += __shfl_xor_sync(0xffffffffu, sp, o);
        if (lane == 0) wds[wid] = sp;
        __syncthreads();
        if (t == 0) {
            double tot = 0.0;
#pragma unroll
            for (int i2 = 0; i2 < 32; i2++) tot += wds[i2];
            g_sumpi = tot;
        }
    }
}

// fused: CSR scatter + query-id scatter
__global__ void k_scatter(const int* __restrict__ AE, const int* __restrict__ Q,
                          int E, int EB) {
    if ((int)blockIdx.x < EB) {
        int e = blockIdx.x * 256 + threadIdx.x;
        if (e >= E) return;
        int u = idx_at(AE, 2 * e), v = idx_at(AE, 2 * e + 1);
        float a = g_aval[e];
        int i1 = atomicAdd(&g_rowpos[u], 1); g_cols[i1] = v; g_cvals[i1] = a;
        int i2 = atomicAdd(&g_rowpos[v], 1); g_cols[i2] = u; g_cvals[i2] = a;
    } else {
        int q = (blockIdx.x - EB) * 256 + threadIdx.x;
        if (q >= EQN) return;
        int i = idx_at(Q, 2 * q);
        int idx = atomicAdd(&g_qpos[i], 1);
        g_qid[idx] = q;
    }
}

__global__ void __launch_bounds__(256) k_row(const int* __restrict__ Q) {
    __shared__ float acc[NN];
    __shared__ float s1[8], s2[8];
    int i = blockIdx.x;
    int t = threadIdx.x;
    for (int c = t; c < NN; c += 256) acc[c] = 0.0f;
    __syncthreads();

    int rs = g_rowstart[i], re = g_rowstart[i + 1];
    float idi = g_invd[i];
    int warp = t >> 5, lane = t & 31;
    for (int jj = rs + warp; jj < re; jj += 8) {
        int j = g_cols[jj];
        float sscale = g_cvals[jj] * idi * g_invd[j];
        int js = g_rowstart[j], je = g_rowstart[j + 1];
        for (int kk = js + lane; kk < je; kk += 32)
            atomicAdd(&acc[g_cols[kk]], sscale * g_cvals[kk]);
    }
    __syncthreads();

    float srow = 0.0f, ssq = 0.0f;
    for (int c = t; c < NN; c += 256) {
        float a = acc[c];
        srow += a;
        float dd = a - g_pi[c];
        ssq = fmaf(dd, dd, ssq);
    }
#pragma unroll
    for (int o = 16; o; o >>= 1) {
        srow += __shfl_down_sync(0xffffffffu, srow, o);
        ssq  += __shfl_down_sync(0xffffffffu, ssq, o);
    }
    if (lane == 0) { s1[warp] = srow; s2[warp] = ssq; }
    __syncthreads();
    if (t == 0) {
        float S1 = 0.0f, S2 = 0.0f;
#pragma unroll
        for (int w2 = 0; w2 < 8; w2++) { S1 += s1[w2]; S2 += s2[w2]; }
        float pii = g_pi[i];
        atomicAdd(&g_G1, (double)pii * (double)S1);
        atomicAdd(&g_G2, (double)pii * (double)pii * (double)S2);
    }
    int qs = g_qstart[i], qe = g_qstart[i + 1];
    for (int q = qs + t; q < qe; q += 256) {
        int qq = g_qid[q];
        int j1 = idx_at(Q, 2 * qq + 1);
        g_pval[qq] = acc[j1];
    }
}

__global__ void k_final(const int* __restrict__ Q, float* __restrict__ out) {
    int q = blockIdx.x * 256 + threadIdx.x;
    if (q >= EQN) return;
    double n2 = (double)NN * (double)NN;
    double sp = g_sumpi;
    double mean = (g_G1 - sp * sp) / n2;
    double var = (g_G2 - n2 * mean * mean) / (n2 - 1.0);
    double istd = rsqrt(var);
    int i = idx_at(Q, 2 * q), j = idx_at(Q, 2 * q + 1);
    double r = (double)g_pi[i] * ((double)g_pval[q] - (double)g_pi[j]);
    out[q] = (float)((r - mean) * istd);
}

// ---------------- launch ----------------
extern "C" void kernel_launch(void* const* d_in, const int* in_sizes, int n_in,
                              void* d_out, int out_size) {
    const float* X  = (const float*)d_in[0];
    const float* A  = (const float*)d_in[1];
    const float* S  = (const float*)d_in[2];
    const int*   AE = (const int*)d_in[4];
    const int*   Q  = (const int*)d_in[5];
    const float* W1 = (const float*)d_in[6];
    const float* b1 = (const float*)d_in[7];
    const float* W2 = (const float*)d_in[8];
    const float* b2 = (const float*)d_in[9];
    const float* W3 = (const float*)d_in[10];
    const float* b3 = (const float*)d_in[11];
    float* out = (float*)d_out;
    int E = in_sizes[4] / 2;
    int EB = (E + 255) / 256;
    int QB = EQN / 256;

    k_pre<<<144, 256>>>(X, AE, W1, W2, W3);
    k_mlp<<<(E + 63) / 64, 128>>>(X, AE, b1, b2, b3, E);
    k_edge_qcnt<<<EB + QB, 256>>>(A, S, AE, Q, E, EB);
    k_scan<<<1, 1024>>>();
    k_scatter<<<EB + QB, 256>>>(AE, Q, E, EB);
    k_row<<<NN, 256>>>(Q);
    k_final<<<QB, 256>>>(Q, out);
}

// round 14
// speedup vs baseline: 1.0986x; 1.0764x over previous
#include <cuda_runtime.h>
#include <math.h>
#include <stdint.h>

#define NN   4096
#define DD   128
#define HH   128
#define EQN  16384
#define MAXE 131072
#define MAXNNZ 262144

// ---------------- device scratch ----------------
static __device__ float    g_vals[MAXE];
static __device__ float    g_aval[MAXE];
static __device__ float    g_d[NN];
static __device__ int      g_deg[NN];
static __device__ float    g_invd[NN];
static __device__ float    g_pi[NN];
static __device__ int      g_rowstart[NN + 1];
static __device__ int      g_rowpos[NN];
static __device__ int2     g_pack[MAXNNZ];       // (col, bits(val)) packed CSR
static __device__ int      g_qcnt[NN];
static __device__ int      g_qstart[NN + 1];
static __device__ int      g_qpos[NN];
static __device__ int      g_qid[EQN];
static __device__ float    g_pval[EQN];
static __device__ double   g_G1, g_G2, g_sumpi;
static __device__ float    g_sumd, g_invsumd;
static __device__ float    g_XW[NN * HH];        // X @ W1[:128,:] (fp32, exact)
static __device__ uint32_t g_W1p[HH * HH];       // frag-packed tf32(W1[128:256,:])
static __device__ uint32_t g_W2p[HH * HH];       // frag-packed tf32(W2)
static __device__ float    g_wd[HH];             // W3[:,1]-W3[:,0]
static __device__ int      g_is64;

__device__ __forceinline__ int idx_at(const int* __restrict__ p, int k) {
    return g_is64 ? p[2 * k] : p[k];
}
__device__ __forceinline__ uint32_t tf32r(float f) {
    uint32_t r;
    asm("cvt.rna.tf32.f32 %0, %1;" : "=r"(r) : "f"(f));
    return r;
}
__device__ __forceinline__ void mma_tf32(float* d, const uint32_t* a,
                                         uint32_t b0, uint32_t b1) {
    asm("mma.sync.aligned.m16n8k8.row.col.f32.tf32.tf32.f32 "
        "{%0,%1,%2,%3}, {%4,%5,%6,%7}, {%8,%9}, {%0,%1,%2,%3};"
        : "+f"(d[0]), "+f"(d[1]), "+f"(d[2]), "+f"(d[3])
        : "r"(a[0]), "r"(a[1]), "r"(a[2]), "r"(a[3]), "r"(b0), "r"(b1));
}

// ---------------- k_pre: init (blocks 0..15) + weight prep (16..79) + XW (80..143) ----
__global__ void __launch_bounds__(256) k_pre(const float* __restrict__ X,
                                             const int* __restrict__ AE,
                                             const float* __restrict__ W1,
                                             const float* __restrict__ W2,
                                             const float* __restrict__ W3) {
    int b = blockIdx.x, t = threadIdx.x;
    if (b < 16) {
        int i = b * 256 + t;
        g_d[i] = 1.0f;          // diagonal contribution
        g_deg[i] = 1;
        g_qcnt[i] = 0;
        if (i == 0) {
            g_G1 = 0.0; g_G2 = 0.0; g_sumpi = 0.0;
            g_is64 = (AE[1] == 0) ? 1 : 0;   // strictly upper-tri => e1>=1
        }
        return;
    }
    if (b < 80) {
        int i = (b - 16) * 256 + t;
        int q    = i & 7;
        int lane = (i >> 3) & 31;
        int w    = (i >> 8) & 3;
        int kt   = i >> 10;
        int tig = lane & 3, g = lane >> 2;
        int j = q >> 1, which = q & 1;
        int k = kt * 8 + tig + 4 * which;
        int n = 32 * w + 8 * j + g;
        g_W1p[i] = tf32r(W1[(size_t)(HH + k) * HH + n]);
        g_W2p[i] = tf32r(W2[(size_t)k * HH + n]);
        if (i < HH) g_wd[i] = W3[2 * i + 1] - W3[2 * i];
        return;
    }
    __shared__ float xs[64 * 132];
    int bx = b - 80;
    int r0 = bx * 64;
    {
        int le = t >> 2, c4 = t & 3;
        const float* xr = X + (size_t)(r0 + le) * DD + c4 * 32;
#pragma unroll
        for (int i = 0; i < 32; i++) xs[le * 132 + c4 * 32 + i] = xr[i];
    }
    __syncthreads();
    int col = t & 127, h = t >> 7;
    float acc[32];
#pragma unroll
    for (int e = 0; e < 32; e++) acc[e] = 0.0f;
    for (int k = 0; k < 128; k++) {
        float w = W1[k * 128 + col];
#pragma unroll
        for (int e = 0; e < 32; e++) acc[e] = fmaf(w, xs[(h * 32 + e) * 132 + k], acc[e]);
    }
#pragma unroll
    for (int e = 0; e < 32; e++) g_XW[(size_t)(r0 + h * 32 + e) * 128 + col] = acc[e];
}

// ---- tensor-core edge MLP (R7 topology) + qcnt by min(q0,q1) ----
#define AS 132
__global__ void __launch_bounds__(128) k_mlp(const float* __restrict__ X,
                                             const int* __restrict__ AE,
                                             const int* __restrict__ Q,
                                             const float* __restrict__ b1g,
                                             const float* __restrict__ b2g,
                                             const float* __restrict__ b3g,
                                             int E) {
    __shared__ __align__(16) uint32_t As[64 * AS];
    __shared__ int   su[64], sv[64];
    __shared__ float zsm[64 * 4];
    int t = threadIdx.x;
    int w = t >> 5, lane = t & 31;
    int g = lane >> 2, tig = lane & 3;
    int e0 = blockIdx.x * 64;

    // query row counts by min(q0,q1) (grid >= 128; 128*128 = EQN)
    if ((int)blockIdx.x < 128) {
        int q = blockIdx.x * 128 + t;
        int q0 = idx_at(Q, 2 * q), q1 = idx_at(Q, 2 * q + 1);
        atomicAdd(&g_qcnt[min(q0, q1)], 1);
    }

    if (lane < 16) {
        int le = w * 16 + lane;
        int e = e0 + le;
        int u = 0, v = 0;
        if (e < E) { u = idx_at(AE, 2 * e); v = idx_at(AE, 2 * e + 1); }
        su[le] = u; sv[le] = v;
    }
    __syncwarp();

#pragma unroll 4
    for (int i = 0; i < 16; i++) {
        int le = w * 16 + i;
        float4 xu = ((const float4*)(X + (size_t)su[le] * DD))[lane];
        float4 xv = ((const float4*)(X + (size_t)sv[le] * DD))[lane];
        uint4 f;
        f.x = tf32r(fabsf(xu.x - xv.x));
        f.y = tf32r(fabsf(xu.y - xv.y));
        f.z = tf32r(fabsf(xu.z - xv.z));
        f.w = tf32r(fabsf(xu.w - xv.w));
        *(uint4*)&As[le * AS + 4 * lane] = f;
    }
    __syncthreads();

    float acc[4][4][4];

    {
        float2 bb[4];
#pragma unroll
        for (int j = 0; j < 4; j++) bb[j] = *(const float2*)&b1g[32 * w + 8 * j + 2 * tig];
#pragma unroll
        for (int mt = 0; mt < 4; mt++) {
            int r0 = mt * 16 + g, r1 = r0 + 8;
            int u0 = su[r0], v0 = sv[r0], u1 = su[r1], v1 = sv[r1];
#pragma unroll
            for (int j = 0; j < 4; j++) {
                int c = 32 * w + 8 * j + 2 * tig;
                float2 xu0 = *(const float2*)&g_XW[(size_t)u0 * 128 + c];
                float2 xv0 = *(const float2*)&g_XW[(size_t)v0 * 128 + c];
                float2 xu1 = *(const float2*)&g_XW[(size_t)u1 * 128 + c];
                float2 xv1 = *(const float2*)&g_XW[(size_t)v1 * 128 + c];
                acc[mt][j][0] = bb[j].x + xu0.x + xv0.x;
                acc[mt][j][1] = bb[j].y + xu0.y + xv0.y;
                acc[mt][j][2] = bb[j].x + xu1.x + xv1.x;
                acc[mt][j][3] = bb[j].y + xu1.y + xv1.y;
            }
        }
    }

#pragma unroll
    for (int kt = 0; kt < 16; kt++) {
        int kc = kt * 8 + tig;
        uint32_t a[4][4];
#pragma unroll
        for (int mt = 0; mt < 4; mt++) {
            int r0 = mt * 16 + g;
            a[mt][0] = As[r0 * AS + kc];
            a[mt][1] = As[(r0 + 8) * AS + kc];
            a[mt][2] = As[r0 * AS + kc + 4];
            a[mt][3] = As[(r0 + 8) * AS + kc + 4];
        }
        const uint4* Wp = (const uint4*)(g_W1p + (((kt * 4 + w) * 32 + lane) << 3));
        uint4 wA = Wp[0], wB = Wp[1];
#pragma unroll
        for (int mt = 0; mt < 4; mt++) {
            mma_tf32(acc[mt][0], a[mt], wA.x, wA.y);
            mma_tf32(acc[mt][1], a[mt], wA.z, wA.w);
            mma_tf32(acc[mt][2], a[mt], wB.x, wB.y);
            mma_tf32(acc[mt][3], a[mt], wB.z, wB.w);
        }
    }
    __syncthreads();

#pragma unroll
    for (int mt = 0; mt < 4; mt++) {
        int r0 = mt * 16 + g;
#pragma unroll
        for (int j = 0; j < 4; j++) {
            int c = 32 * w + 8 * j + 2 * tig;
            uint2 p0, p1;
            p0.x = tf32r(fmaxf(acc[mt][j][0], 0.0f));
            p0.y = tf32r(fmaxf(acc[mt][j][1], 0.0f));
            p1.x = tf32r(fmaxf(acc[mt][j][2], 0.0f));
            p1.y = tf32r(fmaxf(acc[mt][j][3], 0.0f));
            *(uint2*)&As[r0 * AS + c] = p0;
            *(uint2*)&As[(r0 + 8) * AS + c] = p1;
        }
    }
    __syncthreads();

    {
#pragma unroll
        for (int j = 0; j < 4; j++) {
            float2 bb = *(const float2*)&b2g[32 * w + 8 * j + 2 * tig];
#pragma unroll
            for (int mt = 0; mt < 4; mt++) {
                acc[mt][j][0] = bb.x; acc[mt][j][1] = bb.y;
                acc[mt][j][2] = bb.x; acc[mt][j][3] = bb.y;
            }
        }
    }
#pragma unroll
    for (int kt = 0; kt < 16; kt++) {
        int kc = kt * 8 + tig;
        uint32_t a[4][4];
#pragma unroll
        for (int mt = 0; mt < 4; mt++) {
            int r0 = mt * 16 + g;
            a[mt][0] = As[r0 * AS + kc];
            a[mt][1] = As[(r0 + 8) * AS + kc];
            a[mt][2] = As[r0 * AS + kc + 4];
            a[mt][3] = As[(r0 + 8) * AS + kc + 4];
        }
        const uint4* Wp = (const uint4*)(g_W2p + (((kt * 4 + w) * 32 + lane) << 3));
        uint4 wA = Wp[0], wB = Wp[1];
#pragma unroll
        for (int mt = 0; mt < 4; mt++) {
            mma_tf32(acc[mt][0], a[mt], wA.x, wA.y);
            mma_tf32(acc[mt][1], a[mt], wA.z, wA.w);
            mma_tf32(acc[mt][2], a[mt], wB.x, wB.y);
            mma_tf32(acc[mt][3], a[mt], wB.z, wB.w);
        }
    }

    float z[4][2];
#pragma unroll
    for (int mt = 0; mt < 4; mt++) { z[mt][0] = 0.0f; z[mt][1] = 0.0f; }
    {
        float2 wdj[4];
#pragma unroll
        for (int j = 0; j < 4; j++) wdj[j] = *(const float2*)&g_wd[32 * w + 8 * j + 2 * tig];
#pragma unroll
        for (int mt = 0; mt < 4; mt++)
#pragma unroll
            for (int j = 0; j < 4; j++) {
                z[mt][0] = fmaf(fmaxf(acc[mt][j][0], 0.0f), wdj[j].x,
                           fmaf(fmaxf(acc[mt][j][1], 0.0f), wdj[j].y, z[mt][0]));
                z[mt][1] = fmaf(fmaxf(acc[mt][j][2], 0.0f), wdj[j].x,
                           fmaf(fmaxf(acc[mt][j][3], 0.0f), wdj[j].y, z[mt][1]));
            }
    }
#pragma unroll
    for (int mt = 0; mt < 4; mt++)
#pragma unroll
        for (int h = 0; h < 2; h++) {
            z[mt][h] += __shfl_xor_sync(0xffffffffu, z[mt][h], 1);
            z[mt][h] += __shfl_xor_sync(0xffffffffu, z[mt][h], 2);
        }
    if (tig == 0) {
#pragma unroll
        for (int mt = 0; mt < 4; mt++)
#pragma unroll
            for (int h = 0; h < 2; h++)
                zsm[(mt * 16 + g + 8 * h) * 4 + w] = z[mt][h];
    }
    __syncthreads();
    if (t < 64) {
        int e = e0 + t;
        if (e < E) {
            float zz = zsm[4 * t] + zsm[4 * t + 1] + zsm[4 * t + 2] + zsm[4 * t + 3]
                     + (b3g[1] - b3g[0]);
            g_vals[e] = 1.0f / (1.0f + __expf(-zz));
        }
    }
}

// fused: edge A_enh accumulation (no query part here — qcnt moved to k_mlp)
__global__ void k_edge(const float* __restrict__ A, const float* __restrict__ S,
                       const int* __restrict__ AE, int E) {
    int e = blockIdx.x * 256 + threadIdx.x;
    if (e >= E) return;
    int u = idx_at(AE, 2 * e), v = idx_at(AE, 2 * e + 1);
    size_t idx = ((size_t)u << 12) + (size_t)v;
    float a = 0.5f * A[idx] + 0.25f * g_vals[e] + 0.25f * S[idx];
    g_aval[e] = a;
    atomicAdd(&g_d[u], a);
    atomicAdd(&g_d[v], a);
    atomicAdd(&g_deg[u], 1);
    atomicAdd(&g_deg[v], 1);
}

// scans (rows, query rows) + sumd only. rowpos reserves slot 0 of each row for diag.
__global__ void __launch_bounds__(1024) k_scan() {
    __shared__ int   wsum[32];
    __shared__ float wfs[32];
    int t = threadIdx.x;
    int lane = t & 31, wid = t >> 5;

    int   deg[4];
    float dv[4];
#pragma unroll
    for (int j = 0; j < 4; j++) {
        deg[j] = g_deg[4 * t + j];
        dv[j] = g_d[4 * t + j];
    }

    // ---- row degree scan ----
    {
        int s = deg[0] + deg[1] + deg[2] + deg[3];
        int incl = s;
#pragma unroll
        for (int o = 1; o < 32; o <<= 1) {
            int x = __shfl_up_sync(0xffffffffu, incl, o);
            if (lane >= o) incl += x;
        }
        if (lane == 31) wsum[wid] = incl;
        __syncthreads();
        if (wid == 0) {
            int ws = wsum[lane];
            int wi = ws;
#pragma unroll
            for (int o = 1; o < 32; o <<= 1) {
                int x = __shfl_up_sync(0xffffffffu, wi, o);
                if (lane >= o) wi += x;
            }
            wsum[lane] = wi - ws;
        }
        __syncthreads();
        int run = wsum[wid] + incl - s;
#pragma unroll
        for (int j = 0; j < 4; j++) {
            g_rowstart[4 * t + j] = run;
            g_rowpos[4 * t + j] = run + 1;   // slot 0 reserved for diagonal
            run += deg[j];
        }
        if (t == 1023) g_rowstart[NN] = run;
    }
    __syncthreads();

    // ---- query count scan ----
    {
        int v[4], s = 0;
#pragma unroll
        for (int j = 0; j < 4; j++) { v[j] = g_qcnt[4 * t + j]; s += v[j]; }
        int incl = s;
#pragma unroll
        for (int o = 1; o < 32; o <<= 1) {
            int x = __shfl_up_sync(0xffffffffu, incl, o);
            if (lane >= o) incl += x;
        }
        if (lane == 31) wsum[wid] = incl;
        __syncthreads();
        if (wid == 0) {
            int ws = wsum[lane];
            int wi = ws;
#pragma unroll
            for (int o = 1; o < 32; o <<= 1) {
                int x = __shfl_up_sync(0xffffffffu, wi, o);
                if (lane >= o) wi += x;
            }
            wsum[lane] = wi - ws;
        }
        __syncthreads();
        int run = wsum[wid] + incl - s;
#pragma unroll
        for (int j = 0; j < 4; j++) { g_qstart[4 * t + j] = run; g_qpos[4 * t + j] = run; run += v[j]; }
        if (t == 1023) g_qstart[NN] = run;
    }
    __syncthreads();

    // ---- sumd ----
    {
        float fs = dv[0] + dv[1] + dv[2] + dv[3];
#pragma unroll
        for (int o = 16; o; o >>= 1) fs += __shfl_xor_sync(0xffffffffu, fs, o);
        if (lane == 0) wfs[wid] = fs;
        __syncthreads();
        if (t == 0) {
            float tot = 0.0f;
#pragma unroll
            for (int i2 = 0; i2 < 32; i2++) tot += wfs[i2];
            g_sumd = tot;
            g_invsumd = 1.0f / tot;
        }
    }
}

// fused: CSR scatter (packed) + query-id scatter (by min) + pi/invd/diag/sumpi (16 blocks)
__global__ void k_scatter(const int* __restrict__ AE, const int* __restrict__ Q,
                          int E, int EB, int QB) {
    int b = blockIdx.x, t = threadIdx.x;
    if (b < EB) {
        int e = b * 256 + t;
        if (e >= E) return;
        int u = idx_at(AE, 2 * e), v = idx_at(AE, 2 * e + 1);
        float a = g_aval[e];
        int av = __float_as_int(a);
        int i1 = atomicAdd(&g_rowpos[u], 1); g_pack[i1] = make_int2(v, av);
        int i2 = atomicAdd(&g_rowpos[v], 1); g_pack[i2] = make_int2(u, av);
    } else if (b < EB + QB) {
        int q = (b - EB) * 256 + t;
        if (q >= EQN) return;
        int q0 = idx_at(Q, 2 * q), q1 = idx_at(Q, 2 * q + 1);
        int idx = atomicAdd(&g_qpos[min(q0, q1)], 1);
        g_qid[idx] = q;
    } else {
        __shared__ double sps[8];
        int i = (b - EB - QB) * 256 + t;
        float di = g_d[i];
        float p = di / g_sumd;
        g_pi[i] = p;
        g_invd[i] = 1.0f / di;
        g_pack[g_rowstart[i]] = make_int2(i, __float_as_int(1.0f));
        double sp = (double)p;
#pragma unroll
        for (int o = 16; o; o >>= 1) sp += __shfl_xor_sync(0xffffffffu, sp, o);
        int lane = t & 31, wd2 = t >> 5;
        if (lane == 0) sps[wd2] = sp;
        __syncthreads();
        if (t == 0) {
            double tot = 0.0;
#pragma unroll
            for (int k = 0; k < 8; k++) tot += sps[k];
            atomicAdd(&g_sumpi, tot);
        }
    }
}

// Upper-triangle W row: W = (1/sumd) A D^-1 A (symmetric). Scatter cols >= i only.
__global__ void __launch_bounds__(256) k_row(const int* __restrict__ Q) {
    __shared__ float acc[NN];
    __shared__ float s1[8], s2[8];
    int i = blockIdx.x;
    int t = threadIdx.x;
    for (int c = i + t; c < NN; c += 256) acc[c] = 0.0f;
    __syncthreads();

    float isd = g_invsumd;
    int rs = g_rowstart[i], re = g_rowstart[i + 1];
    int warp = t >> 5, lane = t & 31;
    for (int jj = rs + warp; jj < re; jj += 8) {
        int2 pj = g_pack[jj];
        int j = pj.x;
        float sscale = __int_as_float(pj.y) * g_invd[j] * isd;
        int js = g_rowstart[j], je = g_rowstart[j + 1];
        for (int kk = js + lane; kk < je; kk += 32) {
            int2 pk = g_pack[kk];
            if (pk.x >= i)
                atomicAdd(&acc[pk.x], sscale * __int_as_float(pk.y));
        }
    }
    __syncthreads();

    float pii = g_pi[i];
    float srow = 0.0f, ssq = 0.0f;
    for (int c = i + t; c < NN; c += 256) {
        float wv = acc[c];
        float dd = wv - pii * g_pi[c];
        float wt = (c == i) ? 1.0f : 2.0f;
        srow = fmaf(wt, wv, srow);
        ssq = fmaf(wt * dd, dd, ssq);
    }
#pragma unroll
    for (int o = 16; o; o >>= 1) {
        srow += __shfl_down_sync(0xffffffffu, srow, o);
        ssq  += __shfl_down_sync(0xffffffffu, ssq, o);
    }
    if (lane == 0) { s1[warp] = srow; s2[warp] = ssq; }
    __syncthreads();
    if (t == 0) {
        float S1 = 0.0f, S2 = 0.0f;
#pragma unroll
        for (int w2 = 0; w2 < 8; w2++) { S1 += s1[w2]; S2 += s2[w2]; }
        atomicAdd(&g_G1, (double)S1);
        atomicAdd(&g_G2, (double)S2);
    }
    int qs = g_qstart[i], qe = g_qstart[i + 1];
    for (int q = qs + t; q < qe; q += 256) {
        int qq = g_qid[q];
        int q0 = idx_at(Q, 2 * qq), q1 = idx_at(Q, 2 * qq + 1);
        g_pval[qq] = acc[max(q0, q1)];
    }
}

__global__ void k_final(const int* __restrict__ Q, float* __restrict__ out) {
    int q = blockIdx.x * 256 + threadIdx.x;
    if (q >= EQN) return;
    double n2 = (double)NN * (double)NN;
    double sp = g_sumpi;
    double mean = (g_G1 - sp * sp) / n2;
    double var = (g_G2 - n2 * mean * mean) / (n2 - 1.0);
    double istd = rsqrt(var);
    int i = idx_at(Q, 2 * q), j = idx_at(Q, 2 * q + 1);
    double r = (double)g_pval[q] - (double)g_pi[i] * (double)g_pi[j];
    out[q] = (float)((r - mean) * istd);
}

// ---------------- launch ----------------
extern "C" void kernel_launch(void* const* d_in, const int* in_sizes, int n_in,
                              void* d_out, int out_size) {
    const float* X  = (const float*)d_in[0];
    const float* A  = (const float*)d_in[1];
    const float* S  = (const float*)d_in[2];
    const int*   AE = (const int*)d_in[4];
    const int*   Q  = (const int*)d_in[5];
    const float* W1 = (const float*)d_in[6];
    const float* b1 = (const float*)d_in[7];
    const float* W2 = (const float*)d_in[8];
    const float* b2 = (const float*)d_in[9];
    const float* W3 = (const float*)d_in[10];
    const float* b3 = (const float*)d_in[11];
    float* out = (float*)d_out;
    int E = in_sizes[4] / 2;
    int EB = (E + 255) / 256;
    int QB = EQN / 256;

    k_pre<<<144, 256>>>(X, AE, W1, W2, W3);
    k_mlp<<<(E + 63) / 64, 128>>>(X, AE, Q, b1, b2, b3, E);
    k_edge<<<EB, 256>>>(A, S, AE, E);
    k_scan<<<1, 1024>>>();
    k_scatter<<<EB + QB + 16, 256>>>(AE, Q, E, EB, QB);
    k_row<<<NN, 256>>>(Q);
    k_final<<<QB, 256>>>(Q, out);
}

// round 15
// speedup vs baseline: 1.2313x; 1.1208x over previous
#include <cuda_runtime.h>
#include <math.h>
#include <stdint.h>

#define NN   4096
#define DD   128
#define HH   128
#define EQN  16384
#define MAXE 131072
#define MAXNNZ 262144

// ---------------- device scratch ----------------
static __device__ float    g_vals[MAXE];
static __device__ float    g_aval[MAXE];
static __device__ float    g_d[NN];
static __device__ int      g_deg[NN];
static __device__ float    g_invd[NN];
static __device__ float    g_pi[NN];
static __device__ int      g_rowstart[NN + 1];
static __device__ int      g_rowpos[NN];
static __device__ int2     g_pack[MAXNNZ];       // (col, bits(val)) packed CSR
static __device__ int      g_qcnt[NN];
static __device__ int      g_qstart[NN + 1];
static __device__ int      g_qpos[NN];
static __device__ int      g_qid[EQN];
static __device__ float    g_pval[EQN];
static __device__ double   g_G1, g_G2, g_sumpi;
static __device__ float    g_sumd, g_invsumd;
static __device__ float    g_XW[NN * HH];        // X @ W1[:128,:] (fp32, exact)
static __device__ uint32_t g_W1p[HH * HH];       // frag-packed tf32(W1[128:256,:])
static __device__ uint32_t g_W2p[HH * HH];       // frag-packed tf32(W2)
static __device__ float    g_wd[HH];             // W3[:,1]-W3[:,0]
static __device__ int      g_is64;

__device__ __forceinline__ int idx_at(const int* __restrict__ p, int k) {
    return g_is64 ? p[2 * k] : p[k];
}
__device__ __forceinline__ uint32_t tf32r(float f) {
    uint32_t r;
    asm("cvt.rna.tf32.f32 %0, %1;" : "=r"(r) : "f"(f));
    return r;
}
__device__ __forceinline__ void mma_tf32(float* d, const uint32_t* a,
                                         uint32_t b0, uint32_t b1) {
    asm("mma.sync.aligned.m16n8k8.row.col.f32.tf32.tf32.f32 "
        "{%0,%1,%2,%3}, {%4,%5,%6,%7}, {%8,%9}, {%0,%1,%2,%3};"
        : "+f"(d[0]), "+f"(d[1]), "+f"(d[2]), "+f"(d[3])
        : "r"(a[0]), "r"(a[1]), "r"(a[2]), "r"(a[3]), "r"(b0), "r"(b1));
}
// f32x2 helpers
__device__ __forceinline__ unsigned long long pk2(float lo, float hi) {
    unsigned long long r;
    asm("mov.b64 %0, {%1, %2};" : "=l"(r) : "f"(lo), "f"(hi));
    return r;
}
__device__ __forceinline__ void upk2(unsigned long long v, float& lo, float& hi) {
    asm("mov.b64 {%0, %1}, %2;" : "=f"(lo), "=f"(hi) : "l"(v));
}
__device__ __forceinline__ void ffma2(unsigned long long& acc,
                                      unsigned long long a, unsigned long long b) {
    asm("fma.rn.f32x2 %0, %1, %2, %0;" : "+l"(acc) : "l"(a), "l"(b));
}

// ---------------- k_pre: init (0..15) + weight prep (16..79) + XW f32x2 (80..143) ----
__global__ void __launch_bounds__(256) k_pre(const float* __restrict__ X,
                                             const int* __restrict__ AE,
                                             const float* __restrict__ W1,
                                             const float* __restrict__ W2,
                                             const float* __restrict__ W3) {
    int b = blockIdx.x, t = threadIdx.x;
    if (b < 16) {
        int i = b * 256 + t;
        g_d[i] = 1.0f;
        g_deg[i] = 1;
        g_qcnt[i] = 0;
        if (i == 0) {
            g_G1 = 0.0; g_G2 = 0.0; g_sumpi = 0.0;
            g_is64 = (AE[1] == 0) ? 1 : 0;
        }
        return;
    }
    if (b < 80) {
        int i = (b - 16) * 256 + t;
        int q    = i & 7;
        int lane = (i >> 3) & 31;
        int w    = (i >> 8) & 3;
        int kt   = i >> 10;
        int tig = lane & 3, g = lane >> 2;
        int j = q >> 1, which = q & 1;
        int k = kt * 8 + tig + 4 * which;
        int n = 32 * w + 8 * j + g;
        g_W1p[i] = tf32r(W1[(size_t)(HH + k) * HH + n]);
        g_W2p[i] = tf32r(W2[(size_t)k * HH + n]);
        if (i < HH) g_wd[i] = W3[2 * i + 1] - W3[2 * i];
        return;
    }
    // ---- XW = X @ W1[0:128,:], 64 rows per block, f32x2 with transposed xs ----
    __shared__ float xs[128 * 66];   // xs[k][row], stride 66 (even -> 8B-aligned pairs)
    int bx = b - 80;
    int r0 = bx * 64;
    {
        int le = t >> 2, c4 = t & 3;
        const float* xr = X + (size_t)(r0 + le) * DD + c4 * 32;
#pragma unroll
        for (int i = 0; i < 32; i++) xs[(c4 * 32 + i) * 66 + le] = xr[i];
    }
    __syncthreads();
    int col = t & 127, h = t >> 7;   // h: row-half 0..31 / 32..63
    unsigned long long acc[16];
#pragma unroll
    for (int p = 0; p < 16; p++) acc[p] = 0ull;
    for (int k = 0; k < 128; k++) {
        float wv = W1[k * 128 + col];
        unsigned long long wp = pk2(wv, wv);
        const double* fp = (const double*)&xs[k * 66 + h * 32];
#pragma unroll
        for (int p = 0; p < 16; p++)
            ffma2(acc[p], __double_as_longlong(fp[p]), wp);
    }
#pragma unroll
    for (int p = 0; p < 16; p++) {
        float lo, hi;
        upk2(acc[p], lo, hi);
        g_XW[(size_t)(r0 + h * 32 + 2 * p) * 128 + col] = lo;
        g_XW[(size_t)(r0 + h * 32 + 2 * p + 1) * 128 + col] = hi;
    }
}

// ---- tensor-core edge MLP (R7 topology) + qcnt by min(q0,q1) ----
#define AS 132
__global__ void __launch_bounds__(128) k_mlp(const float* __restrict__ X,
                                             const int* __restrict__ AE,
                                             const int* __restrict__ Q,
                                             const float* __restrict__ b1g,
                                             const float* __restrict__ b2g,
                                             const float* __restrict__ b3g,
                                             int E) {
    __shared__ __align__(16) uint32_t As[64 * AS];
    __shared__ int   su[64], sv[64];
    __shared__ float zsm[64 * 4];
    int t = threadIdx.x;
    int w = t >> 5, lane = t & 31;
    int g = lane >> 2, tig = lane & 3;
    int e0 = blockIdx.x * 64;

    if ((int)blockIdx.x < 128) {
        int q = blockIdx.x * 128 + t;
        int q0 = idx_at(Q, 2 * q), q1 = idx_at(Q, 2 * q + 1);
        atomicAdd(&g_qcnt[min(q0, q1)], 1);
    }

    if (lane < 16) {
        int le = w * 16 + lane;
        int e = e0 + le;
        int u = 0, v = 0;
        if (e < E) { u = idx_at(AE, 2 * e); v = idx_at(AE, 2 * e + 1); }
        su[le] = u; sv[le] = v;
    }
    __syncwarp();

#pragma unroll 4
    for (int i = 0; i < 16; i++) {
        int le = w * 16 + i;
        float4 xu = ((const float4*)(X + (size_t)su[le] * DD))[lane];
        float4 xv = ((const float4*)(X + (size_t)sv[le] * DD))[lane];
        uint4 f;
        f.x = tf32r(fabsf(xu.x - xv.x));
        f.y = tf32r(fabsf(xu.y - xv.y));
        f.z = tf32r(fabsf(xu.z - xv.z));
        f.w = tf32r(fabsf(xu.w - xv.w));
        *(uint4*)&As[le * AS + 4 * lane] = f;
    }
    __syncthreads();

    float acc[4][4][4];

    {
        float2 bb[4];
#pragma unroll
        for (int j = 0; j < 4; j++) bb[j] = *(const float2*)&b1g[32 * w + 8 * j + 2 * tig];
#pragma unroll
        for (int mt = 0; mt < 4; mt++) {
            int r0 = mt * 16 + g, r1 = r0 + 8;
            int u0 = su[r0], v0 = sv[r0], u1 = su[r1], v1 = sv[r1];
#pragma unroll
            for (int j = 0; j < 4; j++) {
                int c = 32 * w + 8 * j + 2 * tig;
                float2 xu0 = *(const float2*)&g_XW[(size_t)u0 * 128 + c];
                float2 xv0 = *(const float2*)&g_XW[(size_t)v0 * 128 + c];
                float2 xu1 = *(const float2*)&g_XW[(size_t)u1 * 128 + c];
                float2 xv1 = *(const float2*)&g_XW[(size_t)v1 * 128 + c];
                acc[mt][j][0] = bb[j].x + xu0.x + xv0.x;
                acc[mt][j][1] = bb[j].y + xu0.y + xv0.y;
                acc[mt][j][2] = bb[j].x + xu1.x + xv1.x;
                acc[mt][j][3] = bb[j].y + xu1.y + xv1.y;
            }
        }
    }

#pragma unroll
    for (int kt = 0; kt < 16; kt++) {
        int kc = kt * 8 + tig;
        uint32_t a[4][4];
#pragma unroll
        for (int mt = 0; mt < 4; mt++) {
            int r0 = mt * 16 + g;
            a[mt][0] = As[r0 * AS + kc];
            a[mt][1] = As[(r0 + 8) * AS + kc];
            a[mt][2] = As[r0 * AS + kc + 4];
            a[mt][3] = As[(r0 + 8) * AS + kc + 4];
        }
        const uint4* Wp = (const uint4*)(g_W1p + (((kt * 4 + w) * 32 + lane) << 3));
        uint4 wA = Wp[0], wB = Wp[1];
#pragma unroll
        for (int mt = 0; mt < 4; mt++) {
            mma_tf32(acc[mt][0], a[mt], wA.x, wA.y);
            mma_tf32(acc[mt][1], a[mt], wA.z, wA.w);
            mma_tf32(acc[mt][2], a[mt], wB.x, wB.y);
            mma_tf32(acc[mt][3], a[mt], wB.z, wB.w);
        }
    }
    __syncthreads();

#pragma unroll
    for (int mt = 0; mt < 4; mt++) {
        int r0 = mt * 16 + g;
#pragma unroll
        for (int j = 0; j < 4; j++) {
            int c = 32 * w + 8 * j + 2 * tig;
            uint2 p0, p1;
            p0.x = tf32r(fmaxf(acc[mt][j][0], 0.0f));
            p0.y = tf32r(fmaxf(acc[mt][j][1], 0.0f));
            p1.x = tf32r(fmaxf(acc[mt][j][2], 0.0f));
            p1.y = tf32r(fmaxf(acc[mt][j][3], 0.0f));
            *(uint2*)&As[r0 * AS + c] = p0;
            *(uint2*)&As[(r0 + 8) * AS + c] = p1;
        }
    }
    __syncthreads();

    {
#pragma unroll
        for (int j = 0; j < 4; j++) {
            float2 bb = *(const float2*)&b2g[32 * w + 8 * j + 2 * tig];
#pragma unroll
            for (int mt = 0; mt < 4; mt++) {
                acc[mt][j][0] = bb.x; acc[mt][j][1] = bb.y;
                acc[mt][j][2] = bb.x; acc[mt][j][3] = bb.y;
            }
        }
    }
#pragma unroll
    for (int kt = 0; kt < 16; kt++) {
        int kc = kt * 8 + tig;
        uint32_t a[4][4];
#pragma unroll
        for (int mt = 0; mt < 4; mt++) {
            int r0 = mt * 16 + g;
            a[mt][0] = As[r0 * AS + kc];
            a[mt][1] = As[(r0 + 8) * AS + kc];
            a[mt][2] = As[r0 * AS + kc + 4];
            a[mt][3] = As[(r0 + 8) * AS + kc + 4];
        }
        const uint4* Wp = (const uint4*)(g_W2p + (((kt * 4 + w) * 32 + lane) << 3));
        uint4 wA = Wp[0], wB = Wp[1];
#pragma unroll
        for (int mt = 0; mt < 4; mt++) {
            mma_tf32(acc[mt][0], a[mt], wA.x, wA.y);
            mma_tf32(acc[mt][1], a[mt], wA.z, wA.w);
            mma_tf32(acc[mt][2], a[mt], wB.x, wB.y);
            mma_tf32(acc[mt][3], a[mt], wB.z, wB.w);
        }
    }

    float z[4][2];
#pragma unroll
    for (int mt = 0; mt < 4; mt++) { z[mt][0] = 0.0f; z[mt][1] = 0.0f; }
    {
        float2 wdj[4];
#pragma unroll
        for (int j = 0; j < 4; j++) wdj[j] = *(const float2*)&g_wd[32 * w + 8 * j + 2 * tig];
#pragma unroll
        for (int mt = 0; mt < 4; mt++)
#pragma unroll
            for (int j = 0; j < 4; j++) {
                z[mt][0] = fmaf(fmaxf(acc[mt][j][0], 0.0f), wdj[j].x,
                           fmaf(fmaxf(acc[mt][j][1], 0.0f), wdj[j].y, z[mt][0]));
                z[mt][1] = fmaf(fmaxf(acc[mt][j][2], 0.0f), wdj[j].x,
                           fmaf(fmaxf(acc[mt][j][3], 0.0f), wdj[j].y, z[mt][1]));
            }
    }
#pragma unroll
    for (int mt = 0; mt < 4; mt++)
#pragma unroll
        for (int h = 0; h < 2; h++) {
            z[mt][h] += __shfl_xor_sync(0xffffffffu, z[mt][h], 1);
            z[mt][h] += __shfl_xor_sync(0xffffffffu, z[mt][h], 2);
        }
    if (tig == 0) {
#pragma unroll
        for (int mt = 0; mt < 4; mt++)
#pragma unroll
            for (int h = 0; h < 2; h++)
                zsm[(mt * 16 + g + 8 * h) * 4 + w] = z[mt][h];
    }
    __syncthreads();
    if (t < 64) {
        int e = e0 + t;
        if (e < E) {
            float zz = zsm[4 * t] + zsm[4 * t + 1] + zsm[4 * t + 2] + zsm[4 * t + 3]
                     + (b3g[1] - b3g[0]);
            g_vals[e] = 1.0f / (1.0f + __expf(-zz));
        }
    }
}

// edge A_enh accumulation, 2 edges/thread with batched loads
__global__ void k_edge(const float* __restrict__ A, const float* __restrict__ S,
                       const int* __restrict__ AE, int E) {
    int base = (blockIdx.x * 256 + threadIdx.x) * 2;
    bool ok0 = base < E, ok1 = base + 1 < E;
    if (!ok0) return;
    int u0 = idx_at(AE, 2 * base), v0 = idx_at(AE, 2 * base + 1);
    int u1 = 0, v1 = 0;
    if (ok1) { u1 = idx_at(AE, 2 * base + 2); v1 = idx_at(AE, 2 * base + 3); }
    size_t idx0 = ((size_t)u0 << 12) + (size_t)v0;
    size_t idx1 = ((size_t)u1 << 12) + (size_t)v1;
    float a0 = A[idx0], s0 = S[idx0];
    float a1 = 0.0f, s1v = 0.0f;
    if (ok1) { a1 = A[idx1]; s1v = S[idx1]; }
    {
        float a = 0.5f * a0 + 0.25f * g_vals[base] + 0.25f * s0;
        g_aval[base] = a;
        atomicAdd(&g_d[u0], a);
        atomicAdd(&g_d[v0], a);
        atomicAdd(&g_deg[u0], 1);
        atomicAdd(&g_deg[v0], 1);
    }
    if (ok1) {
        float a = 0.5f * a1 + 0.25f * g_vals[base + 1] + 0.25f * s1v;
        g_aval[base + 1] = a;
        atomicAdd(&g_d[u1], a);
        atomicAdd(&g_d[v1], a);
        atomicAdd(&g_deg[u1], 1);
        atomicAdd(&g_deg[v1], 1);
    }
}

// scans (rows, query rows) + sumd only. rowpos reserves slot 0 for diag.
__global__ void __launch_bounds__(1024) k_scan() {
    __shared__ int   wsum[32];
    __shared__ float wfs[32];
    int t = threadIdx.x;
    int lane = t & 31, wid = t >> 5;

    int   deg[4];
    float dv[4];
#pragma unroll
    for (int j = 0; j < 4; j++) {
        deg[j] = g_deg[4 * t + j];
        dv[j] = g_d[4 * t + j];
    }

    {
        int s = deg[0] + deg[1] + deg[2] + deg[3];
        int incl = s;
#pragma unroll
        for (int o = 1; o < 32; o <<= 1) {
            int x = __shfl_up_sync(0xffffffffu, incl, o);
            if (lane >= o) incl += x;
        }
        if (lane == 31) wsum[wid] = incl;
        __syncthreads();
        if (wid == 0) {
            int ws = wsum[lane];
            int wi = ws;
#pragma unroll
            for (int o = 1; o < 32; o <<= 1) {
                int x = __shfl_up_sync(0xffffffffu, wi, o);
                if (lane >= o) wi += x;
            }
            wsum[lane] = wi - ws;
        }
        __syncthreads();
        int run = wsum[wid] + incl - s;
#pragma unroll
        for (int j = 0; j < 4; j++) {
            g_rowstart[4 * t + j] = run;
            g_rowpos[4 * t + j] = run + 1;
            run += deg[j];
        }
        if (t == 1023) g_rowstart[NN] = run;
    }
    __syncthreads();

    {
        int v[4], s = 0;
#pragma unroll
        for (int j = 0; j < 4; j++) { v[j] = g_qcnt[4 * t + j]; s += v[j]; }
        int incl = s;
#pragma unroll
        for (int o = 1; o < 32; o <<= 1) {
            int x = __shfl_up_sync(0xffffffffu, incl, o);
            if (lane >= o) incl += x;
        }
        if (lane == 31) wsum[wid] = incl;
        __syncthreads();
        if (wid == 0) {
            int ws = wsum[lane];
            int wi = ws;
#pragma unroll
            for (int o = 1; o < 32; o <<= 1) {
                int x = __shfl_up_sync(0xffffffffu, wi, o);
                if (lane >= o) wi += x;
            }
            wsum[lane] = wi - ws;
        }
        __syncthreads();
        int run = wsum[wid] + incl - s;
#pragma unroll
        for (int j = 0; j < 4; j++) { g_qstart[4 * t + j] = run; g_qpos[4 * t + j] = run; run += v[j]; }
        if (t == 1023) g_qstart[NN] = run;
    }
    __syncthreads();

    {
        float fs = dv[0] + dv[1] + dv[2] + dv[3];
#pragma unroll
        for (int o = 16; o; o >>= 1) fs += __shfl_xor_sync(0xffffffffu, fs, o);
        if (lane == 0) wfs[wid] = fs;
        __syncthreads();
        if (t == 0) {
            float tot = 0.0f;
#pragma unroll
            for (int i2 = 0; i2 < 32; i2++) tot += wfs[i2];
            g_sumd = tot;
            g_invsumd = 1.0f / tot;
        }
    }
}

// fused: CSR scatter (packed) + query-id scatter (by min) + pi/invd/diag/sumpi
__global__ void k_scatter(const int* __restrict__ AE, const int* __restrict__ Q,
                          int E, int EB, int QB) {
    int b = blockIdx.x, t = threadIdx.x;
    if (b < EB) {
        int e = b * 256 + t;
        if (e >= E) return;
        int u = idx_at(AE, 2 * e), v = idx_at(AE, 2 * e + 1);
        float a = g_aval[e];
        int av = __float_as_int(a);
        int i1 = atomicAdd(&g_rowpos[u], 1); g_pack[i1] = make_int2(v, av);
        int i2 = atomicAdd(&g_rowpos[v], 1); g_pack[i2] = make_int2(u, av);
    } else if (b < EB + QB) {
        int q = (b - EB) * 256 + t;
        if (q >= EQN) return;
        int q0 = idx_at(Q, 2 * q), q1 = idx_at(Q, 2 * q + 1);
        int idx = atomicAdd(&g_qpos[min(q0, q1)], 1);
        g_qid[idx] = q;
    } else {
        __shared__ double sps[8];
        int i = (b - EB - QB) * 256 + t;
        float di = g_d[i];
        float p = di / g_sumd;
        g_pi[i] = p;
        g_invd[i] = 1.0f / di;
        g_pack[g_rowstart[i]] = make_int2(i, __float_as_int(1.0f));
        double sp = (double)p;
#pragma unroll
        for (int o = 16; o; o >>= 1) sp += __shfl_xor_sync(0xffffffffu, sp, o);
        int lane = t & 31, wd2 = t >> 5;
        if (lane == 0) sps[wd2] = sp;
        __syncthreads();
        if (t == 0) {
            double tot = 0.0;
#pragma unroll
            for (int k = 0; k < 8; k++) tot += sps[k];
            atomicAdd(&g_sumpi, tot);
        }
    }
}

// Upper-triangle W row, 512 threads: W = (1/sumd) A D^-1 A (symmetric).
__global__ void __launch_bounds__(512) k_row(const int* __restrict__ Q) {
    __shared__ float acc[NN];
    __shared__ float s1[16], s2[16];
    int i = blockIdx.x;
    int t = threadIdx.x;
    for (int c = i + t; c < NN; c += 512) acc[c] = 0.0f;
    __syncthreads();

    float isd = g_invsumd;
    int rs = g_rowstart[i], re = g_rowstart[i + 1];
    int warp = t >> 5, lane = t & 31;
    for (int jj = rs + warp; jj < re; jj += 16) {
        int2 pj = g_pack[jj];
        int j = pj.x;
        float sscale = __int_as_float(pj.y) * g_invd[j] * isd;
        int js = g_rowstart[j], je = g_rowstart[j + 1];
        for (int kk = js + lane; kk < je; kk += 32) {
            int2 pk = g_pack[kk];
            if (pk.x >= i)
                atomicAdd(&acc[pk.x], sscale * __int_as_float(pk.y));
        }
    }
    __syncthreads();

    float pii = g_pi[i];
    float srow = 0.0f, ssq = 0.0f;
    for (int c = i + t; c < NN; c += 512) {
        float wv = acc[c];
        float dd = wv - pii * g_pi[c];
        float wt = (c == i) ? 1.0f : 2.0f;
        srow = fmaf(wt, wv, srow);
        ssq = fmaf(wt * dd, dd, ssq);
    }
#pragma unroll
    for (int o = 16; o; o >>= 1) {
        srow += __shfl_down_sync(0xffffffffu, srow, o);
        ssq  += __shfl_down_sync(0xffffffffu, ssq, o);
    }
    if (lane == 0) { s1[warp] = srow; s2[warp] = ssq; }
    __syncthreads();
    if (t == 0) {
        float S1 = 0.0f, S2 = 0.0f;
#pragma unroll
        for (int w2 = 0; w2 < 16; w2++) { S1 += s1[w2]; S2 += s2[w2]; }
        atomicAdd(&g_G1, (double)S1);
        atomicAdd(&g_G2, (double)S2);
    }
    int qs = g_qstart[i], qe = g_qstart[i + 1];
    for (int q = qs + t; q < qe; q += 512) {
        int qq = g_qid[q];
        int q0 = idx_at(Q, 2 * qq), q1 = idx_at(Q, 2 * qq + 1);
        g_pval[qq] = acc[max(q0, q1)];
    }
}

__global__ void k_final(const int* __restrict__ Q, float* __restrict__ out) {
    int q = blockIdx.x * 256 + threadIdx.x;
    if (q >= EQN) return;
    double n2 = (double)NN * (double)NN;
    double sp = g_sumpi;
    double mean = (g_G1 - sp * sp) / n2;
    double var = (g_G2 - n2 * mean * mean) / (n2 - 1.0);
    double istd = rsqrt(var);
    int i = idx_at(Q, 2 * q), j = idx_at(Q, 2 * q + 1);
    double r = (double)g_pval[q] - (double)g_pi[i] * (double)g_pi[j];
    out[q] = (float)((r - mean) * istd);
}

// ---------------- launch ----------------
extern "C" void kernel_launch(void* const* d_in, const int* in_sizes, int n_in,
                              void* d_out, int out_size) {
    const float* X  = (const float*)d_in[0];
    const float* A  = (const float*)d_in[1];
    const float* S  = (const float*)d_in[2];
    const int*   AE = (const int*)d_in[4];
    const int*   Q  = (const int*)d_in[5];
    const float* W1 = (const float*)d_in[6];
    const float* b1 = (const float*)d_in[7];
    const float* W2 = (const float*)d_in[8];
    const float* b2 = (const float*)d_in[9];
    const float* W3 = (const float*)d_in[10];
    const float* b3 = (const float*)d_in[11];
    float* out = (float*)d_out;
    int E = in_sizes[4] / 2;
    int EB = (E + 255) / 256;
    int QB = EQN / 256;

    k_pre<<<144, 256>>>(X, AE, W1, W2, W3);
    k_mlp<<<(E + 63) / 64, 128>>>(X, AE, Q, b1, b2, b3, E);
    k_edge<<<(E + 511) / 512, 256>>>(A, S, AE, E);
    k_scan<<<1, 1024>>>();
    k_scatter<<<EB + QB + 16, 256>>>(AE, Q, E, EB, QB);
    k_row<<<NN, 512>>>(Q);
    k_final<<<QB, 256>>>(Q, out);
}

// round 16
// speedup vs baseline: 1.3903x; 1.1291x over previous
#include <cuda_runtime.h>
#include <math.h>
#include <stdint.h>

#define NN   4096
#define DD   128
#define HH   128
#define EQN  16384
#define MAXE 131072
#define MAXNNZ 262144

// ---------------- device scratch ----------------
static __device__ float    g_vals[MAXE];
static __device__ float    g_aval[MAXE];
static __device__ float    g_d[NN];
static __device__ int      g_deg[NN];
static __device__ float    g_invd[NN];
static __device__ float    g_pi[NN];
static __device__ int      g_rowstart[NN + 1];
static __device__ int      g_rowpos[NN];
static __device__ int2     g_pack[MAXNNZ];       // (col, bits(val)) packed CSR
static __device__ int      g_qcnt[NN];
static __device__ int      g_qstart[NN + 1];
static __device__ int      g_qpos[NN];
static __device__ int      g_qid[EQN];
static __device__ float    g_pval[EQN];
static __device__ double   g_G1, g_G2, g_sumpi;
static __device__ float    g_sumd, g_invsumd;
static __device__ float    g_XW[NN * HH];          // X @ W1[:128,:] (fp32, exact)
static __device__ uint32_t g_W1p[HH * HH / 2];     // frag-packed bf16x2(W1[128:256,:])
static __device__ uint32_t g_W2p[HH * HH / 2];     // frag-packed bf16x2(W2)
static __device__ float    g_wd[HH];               // W3[:,1]-W3[:,0]
static __device__ int      g_is64;

__device__ __forceinline__ int idx_at(const int* __restrict__ p, int k) {
    return g_is64 ? p[2 * k] : p[k];
}
// pack two floats as bf16x2 (lo = first arg)
__device__ __forceinline__ uint32_t pkbf(float lo, float hi) {
    uint32_t r;
    asm("cvt.rn.bf16x2.f32 %0, %1, %2;" : "=r"(r) : "f"(hi), "f"(lo));
    return r;
}
__device__ __forceinline__ void mma_bf16(float* d, const uint32_t* a,
                                         uint32_t b0, uint32_t b1) {
    asm("mma.sync.aligned.m16n8k16.row.col.f32.bf16.bf16.f32 "
        "{%0,%1,%2,%3}, {%4,%5,%6,%7}, {%8,%9}, {%0,%1,%2,%3};"
        : "+f"(d[0]), "+f"(d[1]), "+f"(d[2]), "+f"(d[3])
        : "r"(a[0]), "r"(a[1]), "r"(a[2]), "r"(a[3]), "r"(b0), "r"(b1));
}
// f32x2 helpers
__device__ __forceinline__ unsigned long long pk2(float lo, float hi) {
    unsigned long long r;
    asm("mov.b64 %0, {%1, %2};" : "=l"(r) : "f"(lo), "f"(hi));
    return r;
}
__device__ __forceinline__ void upk2(unsigned long long v, float& lo, float& hi) {
    asm("mov.b64 {%0, %1}, %2;" : "=f"(lo), "=f"(hi) : "l"(v));
}
__device__ __forceinline__ void ffma2(unsigned long long& acc,
                                      unsigned long long a, unsigned long long b) {
    asm("fma.rn.f32x2 %0, %1, %2, %0;" : "+l"(acc) : "l"(a), "l"(b));
}

// ---------------- k_pre: init (0..15) + bf16 weight prep (16..47) + XW f32x2 (80..143) ----
__global__ void __launch_bounds__(256) k_pre(const float* __restrict__ X,
                                             const int* __restrict__ AE,
                                             const float* __restrict__ W1,
                                             const float* __restrict__ W2,
                                             const float* __restrict__ W3) {
    int b = blockIdx.x, t = threadIdx.x;
    if (b < 16) {
        int i = b * 256 + t;
        g_d[i] = 1.0f;
        g_deg[i] = 1;
        g_qcnt[i] = 0;
        if (i == 0) {
            g_G1 = 0.0; g_G2 = 0.0; g_sumpi = 0.0;
            g_is64 = (AE[1] == 0) ? 1 : 0;
        }
        return;
    }
    if (b < 80) {
        // bf16 pack: i in [0, 8192). i = ((kt*4 + w)*32 + lane)*8 + q ; q = 2*j + which
        //   b-reg (j,which): n = 32*w + 8*j + g ; k0 = kt*16 + 2*tig + 8*which ; pair (k0, k0+1)
        int i = (b - 16) * 256 + t;
        if (i < HH) g_wd[i] = W3[2 * i + 1] - W3[2 * i];
        if (i >= HH * HH / 2) return;
        int q    = i & 7;
        int lane = (i >> 3) & 31;
        int w    = (i >> 8) & 3;
        int kt   = i >> 10;
        int tig = lane & 3, g = lane >> 2;
        int j = q >> 1, which = q & 1;
        int k0 = kt * 16 + 2 * tig + 8 * which;
        int n = 32 * w + 8 * j + g;
        g_W1p[i] = pkbf(W1[(size_t)(HH + k0) * HH + n], W1[(size_t)(HH + k0 + 1) * HH + n]);
        g_W2p[i] = pkbf(W2[(size_t)k0 * HH + n], W2[(size_t)(k0 + 1) * HH + n]);
        return;
    }
    // ---- XW = X @ W1[0:128,:], 64 rows per block, f32x2 with transposed xs ----
    __shared__ float xs[128 * 66];
    int bx = b - 80;
    int r0 = bx * 64;
    {
        int le = t >> 2, c4 = t & 3;
        const float* xr = X + (size_t)(r0 + le) * DD + c4 * 32;
#pragma unroll
        for (int i = 0; i < 32; i++) xs[(c4 * 32 + i) * 66 + le] = xr[i];
    }
    __syncthreads();
    int col = t & 127, h = t >> 7;
    unsigned long long acc[16];
#pragma unroll
    for (int p = 0; p < 16; p++) acc[p] = 0ull;
    for (int k = 0; k < 128; k++) {
        float wv = W1[k * 128 + col];
        unsigned long long wp = pk2(wv, wv);
        const double* fp = (const double*)&xs[k * 66 + h * 32];
#pragma unroll
        for (int p = 0; p < 16; p++)
            ffma2(acc[p], __double_as_longlong(fp[p]), wp);
    }
#pragma unroll
    for (int p = 0; p < 16; p++) {
        float lo, hi;
        upk2(acc[p], lo, hi);
        g_XW[(size_t)(r0 + h * 32 + 2 * p) * 128 + col] = lo;
        g_XW[(size_t)(r0 + h * 32 + 2 * p + 1) * 128 + col] = hi;
    }
}

// ---- bf16 tensor-core edge MLP: 64 edges/block, 128 threads (4 warps x 32 cols) ----
#define AS2 68    // uint32 stride per edge row (bank = lane+8kt, conflict-free)
__global__ void __launch_bounds__(128) k_mlp(const float* __restrict__ X,
                                             const int* __restrict__ AE,
                                             const int* __restrict__ Q,
                                             const float* __restrict__ b1g,
                                             const float* __restrict__ b2g,
                                             const float* __restrict__ b3g,
                                             int E) {
    __shared__ __align__(16) uint32_t As[64 * AS2];  // bf16x2 features -> h1
    __shared__ int   su[64], sv[64];
    __shared__ float zsm[64 * 4];
    int t = threadIdx.x;
    int w = t >> 5, lane = t & 31;
    int g = lane >> 2, tig = lane & 3;
    int e0 = blockIdx.x * 64;

    if ((int)blockIdx.x < 128) {
        int q = blockIdx.x * 128 + t;
        int q0 = idx_at(Q, 2 * q), q1 = idx_at(Q, 2 * q + 1);
        atomicAdd(&g_qcnt[min(q0, q1)], 1);
    }

    if (lane < 16) {
        int le = w * 16 + lane;
        int e = e0 + le;
        int u = 0, v = 0;
        if (e < E) { u = idx_at(AE, 2 * e); v = idx_at(AE, 2 * e + 1); }
        su[le] = u; sv[le] = v;
    }
    __syncwarp();

    // ---- feature build: |x0-x1| -> bf16 pairs
#pragma unroll 4
    for (int i = 0; i < 16; i++) {
        int le = w * 16 + i;
        float4 xu = ((const float4*)(X + (size_t)su[le] * DD))[lane];
        float4 xv = ((const float4*)(X + (size_t)sv[le] * DD))[lane];
        uint2 f;
        f.x = pkbf(fabsf(xu.x - xv.x), fabsf(xu.y - xv.y));
        f.y = pkbf(fabsf(xu.z - xv.z), fabsf(xu.w - xv.w));
        *(uint2*)&As[le * AS2 + 2 * lane] = f;
    }
    __syncthreads();

    float acc[4][4][4];   // [m-tile][n-subtile j][frag]

    // ---- layer 1 init: b1 + XW[u] + XW[v]  (fp32 exact)
    {
        float2 bb[4];
#pragma unroll
        for (int j = 0; j < 4; j++) bb[j] = *(const float2*)&b1g[32 * w + 8 * j + 2 * tig];
#pragma unroll
        for (int mt = 0; mt < 4; mt++) {
            int r0 = mt * 16 + g, r1 = r0 + 8;
            int u0 = su[r0], v0 = sv[r0], u1 = su[r1], v1 = sv[r1];
#pragma unroll
            for (int j = 0; j < 4; j++) {
                int c = 32 * w + 8 * j + 2 * tig;
                float2 xu0 = *(const float2*)&g_XW[(size_t)u0 * 128 + c];
                float2 xv0 = *(const float2*)&g_XW[(size_t)v0 * 128 + c];
                float2 xu1 = *(const float2*)&g_XW[(size_t)u1 * 128 + c];
                float2 xv1 = *(const float2*)&g_XW[(size_t)v1 * 128 + c];
                acc[mt][j][0] = bb[j].x + xu0.x + xv0.x;
                acc[mt][j][1] = bb[j].y + xu0.y + xv0.y;
                acc[mt][j][2] = bb[j].x + xu1.x + xv1.x;
                acc[mt][j][3] = bb[j].y + xu1.y + xv1.y;
            }
        }
    }

    // ---- layer 1 mma (bf16, K=16 per step, 8 steps)
#pragma unroll
    for (int kt = 0; kt < 8; kt++) {
        int kc = kt * 8 + tig;
        uint32_t a[4][4];
#pragma unroll
        for (int mt = 0; mt < 4; mt++) {
            int r0 = mt * 16 + g;
            a[mt][0] = As[r0 * AS2 + kc];            // rows g,   k pair 2tig
            a[mt][1] = As[(r0 + 8) * AS2 + kc];      // rows g+8
            a[mt][2] = As[r0 * AS2 + kc + 4];        // k pair 2tig+8
            a[mt][3] = As[(r0 + 8) * AS2 + kc + 4];
        }
        const uint4* Wp = (const uint4*)(g_W1p + (((kt * 4 + w) * 32 + lane) << 3));
        uint4 wA = Wp[0], wB = Wp[1];
#pragma unroll
        for (int mt = 0; mt < 4; mt++) {
            mma_bf16(acc[mt][0], a[mt], wA.x, wA.y);
            mma_bf16(acc[mt][1], a[mt], wA.z, wA.w);
            mma_bf16(acc[mt][2], a[mt], wB.x, wB.y);
            mma_bf16(acc[mt][3], a[mt], wB.z, wB.w);
        }
    }
    __syncthreads();

    // relu -> h1 (bf16 pairs) back into As
#pragma unroll
    for (int mt = 0; mt < 4; mt++) {
        int r0 = mt * 16 + g;
#pragma unroll
        for (int j = 0; j < 4; j++) {
            int ci = 16 * w + 4 * j + tig;   // (32w+8j+2tig)/2
            As[r0 * AS2 + ci] =
                pkbf(fmaxf(acc[mt][j][0], 0.0f), fmaxf(acc[mt][j][1], 0.0f));
            As[(r0 + 8) * AS2 + ci] =
                pkbf(fmaxf(acc[mt][j][2], 0.0f), fmaxf(acc[mt][j][3], 0.0f));
        }
    }
    __syncthreads();

    // ---- layer 2 init: b2
    {
#pragma unroll
        for (int j = 0; j < 4; j++) {
            float2 bb = *(const float2*)&b2g[32 * w + 8 * j + 2 * tig];
#pragma unroll
            for (int mt = 0; mt < 4; mt++) {
                acc[mt][j][0] = bb.x; acc[mt][j][1] = bb.y;
                acc[mt][j][2] = bb.x; acc[mt][j][3] = bb.y;
            }
        }
    }
    // ---- layer 2 mma
#pragma unroll
    for (int kt = 0; kt < 8; kt++) {
        int kc = kt * 8 + tig;
        uint32_t a[4][4];
#pragma unroll
        for (int mt = 0; mt < 4; mt++) {
            int r0 = mt * 16 + g;
            a[mt][0] = As[r0 * AS2 + kc];
            a[mt][1] = As[(r0 + 8) * AS2 + kc];
            a[mt][2] = As[r0 * AS2 + kc + 4];
            a[mt][3] = As[(r0 + 8) * AS2 + kc + 4];
        }
        const uint4* Wp = (const uint4*)(g_W2p + (((kt * 4 + w) * 32 + lane) << 3));
        uint4 wA = Wp[0], wB = Wp[1];
#pragma unroll
        for (int mt = 0; mt < 4; mt++) {
            mma_bf16(acc[mt][0], a[mt], wA.x, wA.y);
            mma_bf16(acc[mt][1], a[mt], wA.z, wA.w);
            mma_bf16(acc[mt][2], a[mt], wB.x, wB.y);
            mma_bf16(acc[mt][3], a[mt], wB.z, wB.w);
        }
    }

    // ---- head: z = relu(h2) . wd  (fp32, partial over this warp's 32 cols)
    float z[4][2];
#pragma unroll
    for (int mt = 0; mt < 4; mt++) { z[mt][0] = 0.0f; z[mt][1] = 0.0f; }
    {
        float2 wdj[4];
#pragma unroll
        for (int j = 0; j < 4; j++) wdj[j] = *(const float2*)&g_wd[32 * w + 8 * j + 2 * tig];
#pragma unroll
        for (int mt = 0; mt < 4; mt++)
#pragma unroll
            for (int j = 0; j < 4; j++) {
                z[mt][0] = fmaf(fmaxf(acc[mt][j][0], 0.0f), wdj[j].x,
                           fmaf(fmaxf(acc[mt][j][1], 0.0f), wdj[j].y, z[mt][0]));
                z[mt][1] = fmaf(fmaxf(acc[mt][j][2], 0.0f), wdj[j].x,
                           fmaf(fmaxf(acc[mt][j][3], 0.0f), wdj[j].y, z[mt][1]));
            }
    }
#pragma unroll
    for (int mt = 0; mt < 4; mt++)
#pragma unroll
        for (int h = 0; h < 2; h++) {
            z[mt][h] += __shfl_xor_sync(0xffffffffu, z[mt][h], 1);
            z[mt][h] += __shfl_xor_sync(0xffffffffu, z[mt][h], 2);
        }
    if (tig == 0) {
#pragma unroll
        for (int mt = 0; mt < 4; mt++)
#pragma unroll
            for (int h = 0; h < 2; h++)
                zsm[(mt * 16 + g + 8 * h) * 4 + w] = z[mt][h];
    }
    __syncthreads();
    if (t < 64) {
        int e = e0 + t;
        if (e < E) {
            float zz = zsm[4 * t] + zsm[4 * t + 1] + zsm[4 * t + 2] + zsm[4 * t + 3]
                     + (b3g[1] - b3g[0]);
            g_vals[e] = 1.0f / (1.0f + __expf(-zz));
        }
    }
}

// edge A_enh accumulation, 2 edges/thread with batched loads
__global__ void k_edge(const float* __restrict__ A, const float* __restrict__ S,
                       const int* __restrict__ AE, int E) {
    int base = (blockIdx.x * 256 + threadIdx.x) * 2;
    bool ok0 = base < E, ok1 = base + 1 < E;
    if (!ok0) return;
    int u0 = idx_at(AE, 2 * base), v0 = idx_at(AE, 2 * base + 1);
    int u1 = 0, v1 = 0;
    if (ok1) { u1 = idx_at(AE, 2 * base + 2); v1 = idx_at(AE, 2 * base + 3); }
    size_t idx0 = ((size_t)u0 << 12) + (size_t)v0;
    size_t idx1 = ((size_t)u1 << 12) + (size_t)v1;
    float a0 = A[idx0], s0 = S[idx0];
    float a1 = 0.0f, s1v = 0.0f;
    if (ok1) { a1 = A[idx1]; s1v = S[idx1]; }
    {
        float a = 0.5f * a0 + 0.25f * g_vals[base] + 0.25f * s0;
        g_aval[base] = a;
        atomicAdd(&g_d[u0], a);
        atomicAdd(&g_d[v0], a);
        atomicAdd(&g_deg[u0], 1);
        atomicAdd(&g_deg[v0], 1);
    }
    if (ok1) {
        float a = 0.5f * a1 + 0.25f * g_vals[base + 1] + 0.25f * s1v;
        g_aval[base + 1] = a;
        atomicAdd(&g_d[u1], a);
        atomicAdd(&g_d[v1], a);
        atomicAdd(&g_deg[u1], 1);
        atomicAdd(&g_deg[v1], 1);
    }
}

// scans (rows, query rows) + sumd only. rowpos reserves slot 0 for diag.
__global__ void __launch_bounds__(1024) k_scan() {
    __shared__ int   wsum[32];
    __shared__ float wfs[32];
    int t = threadIdx.x;
    int lane = t & 31, wid = t >> 5;

    int   deg[4];
    float dv[4];
#pragma unroll
    for (int j = 0; j < 4; j++) {
        deg[j] = g_deg[4 * t + j];
        dv[j] = g_d[4 * t + j];
    }

    {
        int s = deg[0] + deg[1] + deg[2] + deg[3];
        int incl = s;
#pragma unroll
        for (int o = 1; o < 32; o <<= 1) {
            int x = __shfl_up_sync(0xffffffffu, incl, o);
            if (lane >= o) incl += x;
        }
        if (lane == 31) wsum[wid] = incl;
        __syncthreads();
        if (wid == 0) {
            int ws = wsum[lane];
            int wi = ws;
#pragma unroll
            for (int o = 1; o < 32; o <<= 1) {
                int x = __shfl_up_sync(0xffffffffu, wi, o);
                if (lane >= o) wi += x;
            }
            wsum[lane] = wi - ws;
        }
        __syncthreads();
        int run = wsum[wid] + incl - s;
#pragma unroll
        for (int j = 0; j < 4; j++) {
            g_rowstart[4 * t + j] = run;
            g_rowpos[4 * t + j] = run + 1;
            run += deg[j];
        }
        if (t == 1023) g_rowstart[NN] = run;
    }
    __syncthreads();

    {
        int v[4], s = 0;
#pragma unroll
        for (int j = 0; j < 4; j++) { v[j] = g_qcnt[4 * t + j]; s += v[j]; }
        int incl = s;
#pragma unroll
        for (int o = 1; o < 32; o <<= 1) {
            int x = __shfl_up_sync(0xffffffffu, incl, o);
            if (lane >= o) incl += x;
        }
        if (lane == 31) wsum[wid] = incl;
        __syncthreads();
        if (wid == 0) {
            int ws = wsum[lane];
            int wi = ws;
#pragma unroll
            for (int o = 1; o < 32; o <<= 1) {
                int x = __shfl_up_sync(0xffffffffu, wi, o);
                if (lane >= o) wi += x;
            }
            wsum[lane] = wi - ws;
        }
        __syncthreads();
        int run = wsum[wid] + incl - s;
#pragma unroll
        for (int j = 0; j < 4; j++) { g_qstart[4 * t + j] = run; g_qpos[4 * t + j] = run; run += v[j]; }
        if (t == 1023) g_qstart[NN] = run;
    }
    __syncthreads();

    {
        float fs = dv[0] + dv[1] + dv[2] + dv[3];
#pragma unroll
        for (int o = 16; o; o >>= 1) fs += __shfl_xor_sync(0xffffffffu, fs, o);
        if (lane == 0) wfs[wid] = fs;
        __syncthreads();
        if (t == 0) {
            float tot = 0.0f;
#pragma unroll
            for (int i2 = 0; i2 < 32; i2++) tot += wfs[i2];
            g_sumd = tot;
            g_invsumd = 1.0f / tot;
        }
    }
}

// fused: CSR scatter (packed) + query-id scatter (by min) + pi/invd/diag/sumpi
__global__ void k_scatter(const int* __restrict__ AE, const int* __restrict__ Q,
                          int E, int EB, int QB) {
    int b = blockIdx.x, t = threadIdx.x;
    if (b < EB) {
        int e = b * 256 + t;
        if (e >= E) return;
        int u = idx_at(AE, 2 * e), v = idx_at(AE, 2 * e + 1);
        float a = g_aval[e];
        int av = __float_as_int(a);
        int i1 = atomicAdd(&g_rowpos[u], 1); g_pack[i1] = make_int2(v, av);
        int i2 = atomicAdd(&g_rowpos[v], 1); g_pack[i2] = make_int2(u, av);
    } else if (b < EB + QB) {
        int q = (b - EB) * 256 + t;
        if (q >= EQN) return;
        int q0 = idx_at(Q, 2 * q), q1 = idx_at(Q, 2 * q + 1);
        int idx = atomicAdd(&g_qpos[min(q0, q1)], 1);
        g_qid[idx] = q;
    } else {
        __shared__ double sps[8];
        int i = (b - EB - QB) * 256 + t;
        float di = g_d[i];
        float p = di / g_sumd;
        g_pi[i] = p;
        g_invd[i] = 1.0f / di;
        g_pack[g_rowstart[i]] = make_int2(i, __float_as_int(1.0f));
        double sp = (double)p;
#pragma unroll
        for (int o = 16; o; o >>= 1) sp += __shfl_xor_sync(0xffffffffu, sp, o);
        int lane = t & 31, wd2 = t >> 5;
        if (lane == 0) sps[wd2] = sp;
        __syncthreads();
        if (t == 0) {
            double tot = 0.0;
#pragma unroll
            for (int k = 0; k < 8; k++) tot += sps[k];
            atomicAdd(&g_sumpi, tot);
        }
    }
}

// Upper-triangle W row, 512 threads: W = (1/sumd) A D^-1 A (symmetric).
__global__ void __launch_bounds__(512) k_row(const int* __restrict__ Q) {
    __shared__ float acc[NN];
    __shared__ float s1[16], s2[16];
    int i = blockIdx.x;
    int t = threadIdx.x;
    for (int c = i + t; c < NN; c += 512) acc[c] = 0.0f;
    __syncthreads();

    float isd = g_invsumd;
    int rs = g_rowstart[i], re = g_rowstart[i + 1];
    int warp = t >> 5, lane = t & 31;
    for (int jj = rs + warp; jj < re; jj += 16) {
        int2 pj = g_pack[jj];
        int j = pj.x;
        float sscale = __int_as_float(pj.y) * g_invd[j] * isd;
        int js = g_rowstart[j], je = g_rowstart[j + 1];
        for (int kk = js + lane; kk < je; kk += 32) {
            int2 pk = g_pack[kk];
            if (pk.x >= i)
                atomicAdd(&acc[pk.x], sscale * __int_as_float(pk.y));
        }
    }
    __syncthreads();

    float pii = g_pi[i];
    float srow = 0.0f, ssq = 0.0f;
    for (int c = i + t; c < NN; c += 512) {
        float wv = acc[c];
        float dd = wv - pii * g_pi[c];
        float wt = (c == i) ? 1.0f : 2.0f;
        srow = fmaf(wt, wv, srow);
        ssq = fmaf(wt * dd, dd, ssq);
    }
#pragma unroll
    for (int o = 16; o; o >>= 1) {
        srow += __shfl_down_sync(0xffffffffu, srow, o);
        ssq  += __shfl_down_sync(0xffffffffu, ssq, o);
    }
    if (lane == 0) { s1[warp] = srow; s2[warp] = ssq; }
    __syncthreads();
    if (t == 0) {
        float S1 = 0.0f, S2 = 0.0f;
#pragma unroll
        for (int w2 = 0; w2 < 16; w2++) { S1 += s1[w2]; S2 += s2[w2]; }
        atomicAdd(&g_G1, (double)S1);
        atomicAdd(&g_G2, (double)S2);
    }
    int qs = g_qstart[i], qe = g_qstart[i + 1];
    for (int q = qs + t; q < qe; q += 512) {
        int qq = g_qid[q];
        int q0 = idx_at(Q, 2 * qq), q1 = idx_at(Q, 2 * qq + 1);
        g_pval[qq] = acc[max(q0, q1)];
    }
}

__global__ void k_final(const int* __restrict__ Q, float* __restrict__ out) {
    int q = blockIdx.x * 256 + threadIdx.x;
    if (q >= EQN) return;
    double n2 = (double)NN * (double)NN;
    double sp = g_sumpi;
    double mean = (g_G1 - sp * sp) / n2;
    double var = (g_G2 - n2 * mean * mean) / (n2 - 1.0);
    double istd = rsqrt(var);
    int i = idx_at(Q, 2 * q), j = idx_at(Q, 2 * q + 1);
    double r = (double)g_pval[q] - (double)g_pi[i] * (double)g_pi[j];
    out[q] = (float)((r - mean) * istd);
}

// ---------------- launch ----------------
extern "C" void kernel_launch(void* const* d_in, const int* in_sizes, int n_in,
                              void* d_out, int out_size) {
    const float* X  = (const float*)d_in[0];
    const float* A  = (const float*)d_in[1];
    const float* S  = (const float*)d_in[2];
    const int*   AE = (const int*)d_in[4];
    const int*   Q  = (const int*)d_in[5];
    const float* W1 = (const float*)d_in[6];
    const float* b1 = (const float*)d_in[7];
    const float* W2 = (const float*)d_in[8];
    const float* b2 = (const float*)d_in[9];
    const float* W3 = (const float*)d_in[10];
    const float* b3 = (const float*)d_in[11];
    float* out = (float*)d_out;
    int E = in_sizes[4] / 2;
    int EB = (E + 255) / 256;
    int QB = EQN / 256;

    k_pre<<<144, 256>>>(X, AE, W1, W2, W3);
    k_mlp<<<(E + 63) / 64, 128>>>(X, AE, Q, b1, b2, b3, E);
    k_edge<<<(E + 511) / 512, 256>>>(A, S, AE, E);
    k_scan<<<1, 1024>>>();
    k_scatter<<<EB + QB + 16, 256>>>(AE, Q, E, EB, QB);
    k_row<<<NN, 512>>>(Q);
    k_final<<<QB, 256>>>(Q, out);
}

// round 17
// speedup vs baseline: 1.4123x; 1.0159x over previous
#include <cuda_runtime.h>
#include <math.h>
#include <stdint.h>

#define NN   4096
#define DD   128
#define HH   128
#define EQN  16384
#define MAXE 131072
#define MAXNNZ 262144

// ---------------- device scratch ----------------
static __device__ float    g_vals[MAXE];
static __device__ float    g_aval[MAXE];
static __device__ float    g_d[NN];
static __device__ int      g_deg[NN];
static __device__ float    g_invd[NN];
static __device__ float    g_pi[NN];
static __device__ int      g_rowstart[NN + 1];
static __device__ int      g_rowpos[NN];
static __device__ int2     g_pack[MAXNNZ];       // (col, bits(val)) packed CSR
static __device__ int      g_qcnt[NN];
static __device__ int      g_qstart[NN + 1];
static __device__ int      g_qpos[NN];
static __device__ int      g_qid[EQN];
static __device__ float    g_pval[EQN];
static __device__ double   g_G1, g_G2, g_sumpi;
static __device__ float    g_sumd, g_invsumd;
static __device__ float    g_XW[NN * HH];          // X @ W1[:128,:] (fp32, exact)
static __device__ uint32_t g_W1p[HH * HH / 2];     // frag-packed bf16x2(W1[128:256,:])
static __device__ uint32_t g_W2p[HH * HH / 2];     // frag-packed bf16x2(W2)
static __device__ float    g_wd[HH];               // W3[:,1]-W3[:,0]
static __device__ int      g_is64;

__device__ __forceinline__ int idx_at(const int* __restrict__ p, int k) {
    return g_is64 ? p[2 * k] : p[k];
}
__device__ __forceinline__ uint32_t pkbf(float lo, float hi) {
    uint32_t r;
    asm("cvt.rn.bf16x2.f32 %0, %1, %2;" : "=r"(r) : "f"(hi), "f"(lo));
    return r;
}
__device__ __forceinline__ void mma_bf16(float* d, const uint32_t* a,
                                         uint32_t b0, uint32_t b1) {
    asm("mma.sync.aligned.m16n8k16.row.col.f32.bf16.bf16.f32 "
        "{%0,%1,%2,%3}, {%4,%5,%6,%7}, {%8,%9}, {%0,%1,%2,%3};"
        : "+f"(d[0]), "+f"(d[1]), "+f"(d[2]), "+f"(d[3])
        : "r"(a[0]), "r"(a[1]), "r"(a[2]), "r"(a[3]), "r"(b0), "r"(b1));
}
__device__ __forceinline__ unsigned long long pk2(float lo, float hi) {
    unsigned long long r;
    asm("mov.b64 %0, {%1, %2};" : "=l"(r) : "f"(lo), "f"(hi));
    return r;
}
__device__ __forceinline__ void upk2(unsigned long long v, float& lo, float& hi) {
    asm("mov.b64 {%0, %1}, %2;" : "=f"(lo), "=f"(hi) : "l"(v));
}
__device__ __forceinline__ void ffma2(unsigned long long& acc,
                                      unsigned long long a, unsigned long long b) {
    asm("fma.rn.f32x2 %0, %1, %2, %0;" : "+l"(acc) : "l"(a), "l"(b));
}

// ---------------- k_pre ----------------
__global__ void __launch_bounds__(256) k_pre(const float* __restrict__ X,
                                             const int* __restrict__ AE,
                                             const float* __restrict__ W1,
                                             const float* __restrict__ W2,
                                             const float* __restrict__ W3) {
    int b = blockIdx.x, t = threadIdx.x;
    if (b < 16) {
        int i = b * 256 + t;
        g_d[i] = 1.0f;
        g_deg[i] = 1;
        g_qcnt[i] = 0;
        if (i == 0) {
            g_G1 = 0.0; g_G2 = 0.0; g_sumpi = 0.0;
            g_is64 = (AE[1] == 0) ? 1 : 0;
        }
        return;
    }
    if (b < 80) {
        int i = (b - 16) * 256 + t;
        if (i < HH) g_wd[i] = W3[2 * i + 1] - W3[2 * i];
        if (i >= HH * HH / 2) return;
        int q    = i & 7;
        int lane = (i >> 3) & 31;
        int w    = (i >> 8) & 3;
        int kt   = i >> 10;
        int tig = lane & 3, g = lane >> 2;
        int j = q >> 1, which = q & 1;
        int k0 = kt * 16 + 2 * tig + 8 * which;
        int n = 32 * w + 8 * j + g;
        g_W1p[i] = pkbf(W1[(size_t)(HH + k0) * HH + n], W1[(size_t)(HH + k0 + 1) * HH + n]);
        g_W2p[i] = pkbf(W2[(size_t)k0 * HH + n], W2[(size_t)(k0 + 1) * HH + n]);
        return;
    }
    __shared__ float xs[128 * 66];
    int bx = b - 80;
    int r0 = bx * 64;
    {
        int le = t >> 2, c4 = t & 3;
        const float* xr = X + (size_t)(r0 + le) * DD + c4 * 32;
#pragma unroll
        for (int i = 0; i < 32; i++) xs[(c4 * 32 + i) * 66 + le] = xr[i];
    }
    __syncthreads();
    int col = t & 127, h = t >> 7;
    unsigned long long acc[16];
#pragma unroll
    for (int p = 0; p < 16; p++) acc[p] = 0ull;
    for (int k = 0; k < 128; k++) {
        float wv = W1[k * 128 + col];
        unsigned long long wp = pk2(wv, wv);
        const double* fp = (const double*)&xs[k * 66 + h * 32];
#pragma unroll
        for (int p = 0; p < 16; p++)
            ffma2(acc[p], __double_as_longlong(fp[p]), wp);
    }
#pragma unroll
    for (int p = 0; p < 16; p++) {
        float lo, hi;
        upk2(acc[p], lo, hi);
        g_XW[(size_t)(r0 + h * 32 + 2 * p) * 128 + col] = lo;
        g_XW[(size_t)(r0 + h * 32 + 2 * p + 1) * 128 + col] = hi;
    }
}

// ---- bf16 tensor-core edge MLP (unchanged from R16) ----
#define AS2 68
__global__ void __launch_bounds__(128) k_mlp(const float* __restrict__ X,
                                             const int* __restrict__ AE,
                                             const int* __restrict__ Q,
                                             const float* __restrict__ b1g,
                                             const float* __restrict__ b2g,
                                             const float* __restrict__ b3g,
                                             int E) {
    __shared__ __align__(16) uint32_t As[64 * AS2];
    __shared__ int   su[64], sv[64];
    __shared__ float zsm[64 * 4];
    int t = threadIdx.x;
    int w = t >> 5, lane = t & 31;
    int g = lane >> 2, tig = lane & 3;
    int e0 = blockIdx.x * 64;

    if ((int)blockIdx.x < 128) {
        int q = blockIdx.x * 128 + t;
        int q0 = idx_at(Q, 2 * q), q1 = idx_at(Q, 2 * q + 1);
        atomicAdd(&g_qcnt[min(q0, q1)], 1);
    }

    if (lane < 16) {
        int le = w * 16 + lane;
        int e = e0 + le;
        int u = 0, v = 0;
        if (e < E) { u = idx_at(AE, 2 * e); v = idx_at(AE, 2 * e + 1); }
        su[le] = u; sv[le] = v;
    }
    __syncwarp();

#pragma unroll 4
    for (int i = 0; i < 16; i++) {
        int le = w * 16 + i;
        float4 xu = ((const float4*)(X + (size_t)su[le] * DD))[lane];
        float4 xv = ((const float4*)(X + (size_t)sv[le] * DD))[lane];
        uint2 f;
        f.x = pkbf(fabsf(xu.x - xv.x), fabsf(xu.y - xv.y));
        f.y = pkbf(fabsf(xu.z - xv.z), fabsf(xu.w - xv.w));
        *(uint2*)&As[le * AS2 + 2 * lane] = f;
    }
    __syncthreads();

    float acc[4][4][4];

    {
        float2 bb[4];
#pragma unroll
        for (int j = 0; j < 4; j++) bb[j] = *(const float2*)&b1g[32 * w + 8 * j + 2 * tig];
#pragma unroll
        for (int mt = 0; mt < 4; mt++) {
            int r0 = mt * 16 + g, r1 = r0 + 8;
            int u0 = su[r0], v0 = sv[r0], u1 = su[r1], v1 = sv[r1];
#pragma unroll
            for (int j = 0; j < 4; j++) {
                int c = 32 * w + 8 * j + 2 * tig;
                float2 xu0 = *(const float2*)&g_XW[(size_t)u0 * 128 + c];
                float2 xv0 = *(const float2*)&g_XW[(size_t)v0 * 128 + c];
                float2 xu1 = *(const float2*)&g_XW[(size_t)u1 * 128 + c];
                float2 xv1 = *(const float2*)&g_XW[(size_t)v1 * 128 + c];
                acc[mt][j][0] = bb[j].x + xu0.x + xv0.x;
                acc[mt][j][1] = bb[j].y + xu0.y + xv0.y;
                acc[mt][j][2] = bb[j].x + xu1.x + xv1.x;
                acc[mt][j][3] = bb[j].y + xu1.y + xv1.y;
            }
        }
    }

#pragma unroll
    for (int kt = 0; kt < 8; kt++) {
        int kc = kt * 8 + tig;
        uint32_t a[4][4];
#pragma unroll
        for (int mt = 0; mt < 4; mt++) {
            int r0 = mt * 16 + g;
            a[mt][0] = As[r0 * AS2 + kc];
            a[mt][1] = As[(r0 + 8) * AS2 + kc];
            a[mt][2] = As[r0 * AS2 + kc + 4];
            a[mt][3] = As[(r0 + 8) * AS2 + kc + 4];
        }
        const uint4* Wp = (const uint4*)(g_W1p + (((kt * 4 + w) * 32 + lane) << 3));
        uint4 wA = Wp[0], wB = Wp[1];
#pragma unroll
        for (int mt = 0; mt < 4; mt++) {
            mma_bf16(acc[mt][0], a[mt], wA.x, wA.y);
            mma_bf16(acc[mt][1], a[mt], wA.z, wA.w);
            mma_bf16(acc[mt][2], a[mt], wB.x, wB.y);
            mma_bf16(acc[mt][3], a[mt], wB.z, wB.w);
        }
    }
    __syncthreads();

#pragma unroll
    for (int mt = 0; mt < 4; mt++) {
        int r0 = mt * 16 + g;
#pragma unroll
        for (int j = 0; j < 4; j++) {
            int ci = 16 * w + 4 * j + tig;
            As[r0 * AS2 + ci] =
                pkbf(fmaxf(acc[mt][j][0], 0.0f), fmaxf(acc[mt][j][1], 0.0f));
            As[(r0 + 8) * AS2 + ci] =
                pkbf(fmaxf(acc[mt][j][2], 0.0f), fmaxf(acc[mt][j][3], 0.0f));
        }
    }
    __syncthreads();

    {
#pragma unroll
        for (int j = 0; j < 4; j++) {
            float2 bb = *(const float2*)&b2g[32 * w + 8 * j + 2 * tig];
#pragma unroll
            for (int mt = 0; mt < 4; mt++) {
                acc[mt][j][0] = bb.x; acc[mt][j][1] = bb.y;
                acc[mt][j][2] = bb.x; acc[mt][j][3] = bb.y;
            }
        }
    }
#pragma unroll
    for (int kt = 0; kt < 8; kt++) {
        int kc = kt * 8 + tig;
        uint32_t a[4][4];
#pragma unroll
        for (int mt = 0; mt < 4; mt++) {
            int r0 = mt * 16 + g;
            a[mt][0] = As[r0 * AS2 + kc];
            a[mt][1] = As[(r0 + 8) * AS2 + kc];
            a[mt][2] = As[r0 * AS2 + kc + 4];
            a[mt][3] = As[(r0 + 8) * AS2 + kc + 4];
        }
        const uint4* Wp = (const uint4*)(g_W2p + (((kt * 4 + w) * 32 + lane) << 3));
        uint4 wA = Wp[0], wB = Wp[1];
#pragma unroll
        for (int mt = 0; mt < 4; mt++) {
            mma_bf16(acc[mt][0], a[mt], wA.x, wA.y);
            mma_bf16(acc[mt][1], a[mt], wA.z, wA.w);
            mma_bf16(acc[mt][2], a[mt], wB.x, wB.y);
            mma_bf16(acc[mt][3], a[mt], wB.z, wB.w);
        }
    }

    float z[4][2];
#pragma unroll
    for (int mt = 0; mt < 4; mt++) { z[mt][0] = 0.0f; z[mt][1] = 0.0f; }
    {
        float2 wdj[4];
#pragma unroll
        for (int j = 0; j < 4; j++) wdj[j] = *(const float2*)&g_wd[32 * w + 8 * j + 2 * tig];
#pragma unroll
        for (int mt = 0; mt < 4; mt++)
#pragma unroll
            for (int j = 0; j < 4; j++) {
                z[mt][0] = fmaf(fmaxf(acc[mt][j][0], 0.0f), wdj[j].x,
                           fmaf(fmaxf(acc[mt][j][1], 0.0f), wdj[j].y, z[mt][0]));
                z[mt][1] = fmaf(fmaxf(acc[mt][j][2], 0.0f), wdj[j].x,
                           fmaf(fmaxf(acc[mt][j][3], 0.0f), wdj[j].y, z[mt][1]));
            }
    }
#pragma unroll
    for (int mt = 0; mt < 4; mt++)
#pragma unroll
        for (int h = 0; h < 2; h++) {
            z[mt][h] += __shfl_xor_sync(0xffffffffu, z[mt][h], 1);
            z[mt][h] += __shfl_xor_sync(0xffffffffu, z[mt][h], 2);
        }
    if (tig == 0) {
#pragma unroll
        for (int mt = 0; mt < 4; mt++)
#pragma unroll
            for (int h = 0; h < 2; h++)
                zsm[(mt * 16 + g + 8 * h) * 4 + w] = z[mt][h];
    }
    __syncthreads();
    if (t < 64) {
        int e = e0 + t;
        if (e < E) {
            float zz = zsm[4 * t] + zsm[4 * t + 1] + zsm[4 * t + 2] + zsm[4 * t + 3]
                     + (b3g[1] - b3g[0]);
            g_vals[e] = 1.0f / (1.0f + __expf(-zz));
        }
    }
}

// edge A_enh accumulation, 4 edges/thread with batched loads
__global__ void k_edge(const float* __restrict__ A, const float* __restrict__ S,
                       const int* __restrict__ AE, int E) {
    int base = (blockIdx.x * 256 + threadIdx.x) * 4;
    if (base >= E) return;
    int u[4], v[4];
    float av[4], sv_[4];
#pragma unroll
    for (int k = 0; k < 4; k++) {
        int e = base + k;
        if (e < E) { u[k] = idx_at(AE, 2 * e); v[k] = idx_at(AE, 2 * e + 1); }
        else { u[k] = 0; v[k] = 0; }
    }
#pragma unroll
    for (int k = 0; k < 4; k++) {
        size_t idx = ((size_t)u[k] << 12) + (size_t)v[k];
        av[k] = A[idx];
        sv_[k] = S[idx];
    }
#pragma unroll
    for (int k = 0; k < 4; k++) {
        int e = base + k;
        if (e < E) {
            float a = 0.5f * av[k] + 0.25f * g_vals[e] + 0.25f * sv_[k];
            g_aval[e] = a;
            atomicAdd(&g_d[u[k]], a);
            atomicAdd(&g_d[v[k]], a);
            atomicAdd(&g_deg[u[k]], 1);
            atomicAdd(&g_deg[v[k]], 1);
        }
    }
}

// packed dual scan: (qcnt<<32)|deg in one chain. + sumd.
__global__ void __launch_bounds__(1024) k_scan() {
    __shared__ unsigned long long wsum[32];
    __shared__ float wfs[32];
    int t = threadIdx.x;
    int lane = t & 31, wid = t >> 5;

    unsigned long long pv[4];
    float dv[4];
#pragma unroll
    for (int j = 0; j < 4; j++) {
        int i = 4 * t + j;
        pv[j] = ((unsigned long long)(unsigned)g_qcnt[i] << 32)
              | (unsigned long long)(unsigned)g_deg[i];
        dv[j] = g_d[i];
    }

    {
        unsigned long long s = pv[0] + pv[1] + pv[2] + pv[3];
        unsigned long long incl = s;
#pragma unroll
        for (int o = 1; o < 32; o <<= 1) {
            unsigned long long x = __shfl_up_sync(0xffffffffu, incl, o);
            if (lane >= o) incl += x;
        }
        if (lane == 31) wsum[wid] = incl;
        __syncthreads();
        if (wid == 0) {
            unsigned long long ws = wsum[lane];
            unsigned long long wi = ws;
#pragma unroll
            for (int o = 1; o < 32; o <<= 1) {
                unsigned long long x = __shfl_up_sync(0xffffffffu, wi, o);
                if (lane >= o) wi += x;
            }
            wsum[lane] = wi - ws;
        }
        __syncthreads();
        unsigned long long run = wsum[wid] + incl - s;
#pragma unroll
        for (int j = 0; j < 4; j++) {
            int i = 4 * t + j;
            int rd = (int)(unsigned)run;
            int rq = (int)(run >> 32);
            g_rowstart[i] = rd;
            g_rowpos[i] = rd + 1;   // slot 0 reserved for diagonal
            g_qstart[i] = rq;
            g_qpos[i] = rq;
            run += pv[j];
        }
        if (t == 1023) {
            g_rowstart[NN] = (int)(unsigned)run;
            g_qstart[NN] = (int)(run >> 32);
        }
    }
    __syncthreads();

    {
        float fs = dv[0] + dv[1] + dv[2] + dv[3];
#pragma unroll
        for (int o = 16; o; o >>= 1) fs += __shfl_xor_sync(0xffffffffu, fs, o);
        if (lane == 0) wfs[wid] = fs;
        __syncthreads();
        if (t == 0) {
            float tot = 0.0f;
#pragma unroll
            for (int i2 = 0; i2 < 32; i2++) tot += wfs[i2];
            g_sumd = tot;
            g_invsumd = 1.0f / tot;
        }
    }
}

// fused: CSR scatter (packed) + query-id scatter (by min) + pi/invd/diag/sumpi
__global__ void k_scatter(const int* __restrict__ AE, const int* __restrict__ Q,
                          int E, int EB, int QB) {
    int b = blockIdx.x, t = threadIdx.x;
    if (b < EB) {
        int e = b * 256 + t;
        if (e >= E) return;
        int u = idx_at(AE, 2 * e), v = idx_at(AE, 2 * e + 1);
        float a = g_aval[e];
        int av = __float_as_int(a);
        int i1 = atomicAdd(&g_rowpos[u], 1); g_pack[i1] = make_int2(v, av);
        int i2 = atomicAdd(&g_rowpos[v], 1); g_pack[i2] = make_int2(u, av);
    } else if (b < EB + QB) {
        int q = (b - EB) * 256 + t;
        if (q >= EQN) return;
        int q0 = idx_at(Q, 2 * q), q1 = idx_at(Q, 2 * q + 1);
        int idx = atomicAdd(&g_qpos[min(q0, q1)], 1);
        g_qid[idx] = q;
    } else {
        __shared__ double sps[8];
        int i = (b - EB - QB) * 256 + t;
        float di = g_d[i];
        float p = di / g_sumd;
        g_pi[i] = p;
        g_invd[i] = 1.0f / di;
        g_pack[g_rowstart[i]] = make_int2(i, __float_as_int(1.0f));
        double sp = (double)p;
#pragma unroll
        for (int o = 16; o; o >>= 1) sp += __shfl_xor_sync(0xffffffffu, sp, o);
        int lane = t & 31, wd2 = t >> 5;
        if (lane == 0) sps[wd2] = sp;
        __syncthreads();
        if (t == 0) {
            double tot = 0.0;
#pragma unroll
            for (int k = 0; k < 8; k++) tot += sps[k];
            atomicAdd(&g_sumpi, tot);
        }
    }
}

// Upper-triangle W row, 512 threads, vectorized zero/scan.
__global__ void __launch_bounds__(512) k_row(const int* __restrict__ Q) {
    __shared__ __align__(16) float acc[NN];
    __shared__ float s1[16], s2[16];
    int i = blockIdx.x;
    int t = threadIdx.x;
    int c40 = i >> 2;                       // first float4 chunk touching [i, NN)
    for (int c4 = c40 + t; c4 < NN / 4; c4 += 512)
        *(float4*)&acc[4 * c4] = make_float4(0.0f, 0.0f, 0.0f, 0.0f);
    __syncthreads();

    float isd = g_invsumd;
    int rs = g_rowstart[i], re = g_rowstart[i + 1];
    int warp = t >> 5, lane = t & 31;
    for (int jj = rs + warp; jj < re; jj += 16) {
        int2 pj = g_pack[jj];
        int j = pj.x;
        float sscale = __int_as_float(pj.y) * g_invd[j] * isd;
        int js = g_rowstart[j], je = g_rowstart[j + 1];
        for (int kk = js + lane; kk < je; kk += 32) {
            int2 pk = g_pack[kk];
            if (pk.x >= i)
                atomicAdd(&acc[pk.x], sscale * __int_as_float(pk.y));
        }
    }
    __syncthreads();

    float pii = g_pi[i];
    float srow = 0.0f, ssq = 0.0f;
    for (int c4 = c40 + t; c4 < NN / 4; c4 += 512) {
        float4 wv = *(const float4*)&acc[4 * c4];
        float4 pv = *(const float4*)&g_pi[4 * c4];
        int cb = 4 * c4;
#pragma unroll
        for (int k = 0; k < 4; k++) {
            int c = cb + k;
            float w = (k == 0) ? wv.x : (k == 1) ? wv.y : (k == 2) ? wv.z : wv.w;
            float p = (k == 0) ? pv.x : (k == 1) ? pv.y : (k == 2) ? pv.z : pv.w;
            float wt = (c < i) ? 0.0f : (c == i) ? 1.0f : 2.0f;
            float dd = w - pii * p;
            srow = fmaf(wt, w, srow);
            ssq = fmaf(wt * dd, dd, ssq);
        }
    }
#pragma unroll
    for (int o = 16; o; o >>= 1) {
        srow += __shfl_down_sync(0xffffffffu, srow, o);
        ssq  += __shfl_down_sync(0xffffffffu, ssq, o);
    }
    if (lane == 0) { s1[warp] = srow; s2[warp] = ssq; }
    __syncthreads();
    if (t == 0) {
        float S1 = 0.0f, S2 = 0.0f;
#pragma unroll
        for (int w2 = 0; w2 < 16; w2++) { S1 += s1[w2]; S2 += s2[w2]; }
        atomicAdd(&g_G1, (double)S1);
        atomicAdd(&g_G2, (double)S2);
    }
    int qs = g_qstart[i], qe = g_qstart[i + 1];
    for (int q = qs + t; q < qe; q += 512) {
        int qq = g_qid[q];
        int q0 = idx_at(Q, 2 * qq), q1 = idx_at(Q, 2 * qq + 1);
        g_pval[qq] = acc[max(q0, q1)];
    }
}

__global__ void k_final(const int* __restrict__ Q, float* __restrict__ out) {
    int q = blockIdx.x * 256 + threadIdx.x;
    if (q >= EQN) return;
    double n2 = (double)NN * (double)NN;
    double sp = g_sumpi;
    double mean = (g_G1 - sp * sp) / n2;
    double var = (g_G2 - n2 * mean * mean) / (n2 - 1.0);
    double istd = rsqrt(var);
    int i = idx_at(Q, 2 * q), j = idx_at(Q, 2 * q + 1);
    double r = (double)g_pval[q] - (double)g_pi[i] * (double)g_pi[j];
    out[q] = (float)((r - mean) * istd);
}

// ---------------- launch ----------------
extern "C" void kernel_launch(void* const* d_in, const int* in_sizes, int n_in,
                              void* d_out, int out_size) {
    const float* X  = (const float*)d_in[0];
    const float* A  = (const float*)d_in[1];
    const float* S  = (const float*)d_in[2];
    const int*   AE = (const int*)d_in[4];
    const int*   Q  = (const int*)d_in[5];
    const float* W1 = (const float*)d_in[6];
    const float* b1 = (const float*)d_in[7];
    const float* W2 = (const float*)d_in[8];
    const float* b2 = (const float*)d_in[9];
    const float* W3 = (const float*)d_in[10];
    const float* b3 = (const float*)d_in[11];
    float* out = (float*)d_out;
    int E = in_sizes[4] / 2;
    int EB = (E + 255) / 256;
    int QB = EQN / 256;

    k_pre<<<144, 256>>>(X, AE, W1, W2, W3);
    k_mlp<<<(E + 63) / 64, 128>>>(X, AE, Q, b1, b2, b3, E);
    k_edge<<<(E + 1023) / 1024, 256>>>(A, S, AE, E);
    k_scan<<<1, 1024>>>();
    k_scatter<<<EB + QB + 16, 256>>>(AE, Q, E, EB, QB);
    k_row<<<NN, 512>>>(Q);
    k_final<<<QB, 256>>>(Q, out);
}